// round 1
// baseline (speedup 1.0000x reference)
#include <cuda_runtime.h>
#include <cstdint>
#include <cstdio>

#define D_MODEL 1024
#define NHEAD   16
#define HDIM    64
#define WIN     128
#define BATCH   4
#define SEQ     4096
#define NW      (SEQ / WIN)            // 32
#define M_TOTAL (BATCH * SEQ)          // 16384
#define QKV_STRIDE ((size_t)M_TOTAL * D_MODEL)  // 16777216

// Scratch (allocation-free rule: device globals)
__device__ float g_qkv[3ull * M_TOTAL * D_MODEL];   // [z][b][w][h][row][d] tiles
__device__ float g_attn[(size_t)M_TOTAL * D_MODEL]; // [b][l][h*64+d] row-major

// ---------------------------------------------------------------------------
// TF32 helpers
// ---------------------------------------------------------------------------
__device__ __forceinline__ uint32_t f2tf32(float f) {
    uint32_t u;
    asm("cvt.rna.tf32.f32 %0, %1;" : "=r"(u) : "f"(f));
    return u;
}

__device__ __forceinline__ void mma_tf32(float c[4], const uint32_t a[4], const uint32_t b[2]) {
    asm volatile(
        "mma.sync.aligned.m16n8k8.row.col.f32.tf32.tf32.f32 "
        "{%0,%1,%2,%3}, {%4,%5,%6,%7}, {%8,%9}, {%0,%1,%2,%3};\n"
        : "+f"(c[0]), "+f"(c[1]), "+f"(c[2]), "+f"(c[3])
        : "r"(a[0]), "r"(a[1]), "r"(a[2]), "r"(a[3]), "r"(b[0]), "r"(b[1]));
}

// ---------------------------------------------------------------------------
// GEMM: Y[M,N] = X[M,K] @ W[N,K]^T + bias   (TN, both K-contiguous)
// MODE 0: z in {0,1,2} selects (q,k,v); X = q/k/v, W = in_proj_w + z*D*D,
//         output scattered into g_qkv attention-tile layout.
// MODE 1: X = g_attn, output row-major into Yp (d_out).
// Block tile 128x128, BK=32, 256 threads (8 warps as 4x2, warp tile 32x64).
// ---------------------------------------------------------------------------
#define BM 128
#define BN 128
#define BK 32
#define SPAD 4   // smem row stride 36 floats (144B, 16B-aligned)

template <int MODE>
__global__ __launch_bounds__(256) void gemm_tn(
    const float* __restrict__ Xq, const float* __restrict__ Xk, const float* __restrict__ Xv,
    const float* __restrict__ Wp, const float* __restrict__ bp, float* __restrict__ Yp)
{
    __shared__ float As[BM][BK + SPAD];
    __shared__ float Bs[BN][BK + SPAD];

    const int z = blockIdx.z;
    const float* X;
    const float* Wz;
    const float* bz;
    if (MODE == 0) {
        X  = (z == 0) ? Xq : (z == 1) ? Xk : Xv;
        Wz = Wp + (size_t)z * D_MODEL * D_MODEL;
        bz = bp + z * D_MODEL;
    } else {
        X  = g_attn;
        Wz = Wp;
        bz = bp;
    }

    const int m0 = blockIdx.y * BM;
    const int n0 = blockIdx.x * BN;
    const int tid  = threadIdx.x;
    const int warp = tid >> 5, lane = tid & 31;
    const int wm = warp >> 1, wn = warp & 1;   // 4x2 warps

    float acc[2][8][4];
#pragma unroll
    for (int mi = 0; mi < 2; mi++)
#pragma unroll
        for (int ni = 0; ni < 8; ni++)
#pragma unroll
            for (int r = 0; r < 4; r++) acc[mi][ni][r] = 0.f;

    const int lrow = tid >> 3;          // 0..31 (plus i*32)
    const int lcol = (tid & 7) * 4;     // 0..28 step 4

    for (int kt = 0; kt < D_MODEL; kt += BK) {
#pragma unroll
        for (int i = 0; i < 4; i++) {
            int r = lrow + i * 32;
            float4 av = *(const float4*)&X [(size_t)(m0 + r) * D_MODEL + kt + lcol];
            *(float4*)&As[r][lcol] = av;
            float4 bv = *(const float4*)&Wz[(size_t)(n0 + r) * D_MODEL + kt + lcol];
            *(float4*)&Bs[r][lcol] = bv;
        }
        __syncthreads();

#pragma unroll
        for (int k8 = 0; k8 < 4; k8++) {
            uint32_t afr[2][4];
            uint32_t bfr[8][2];
            const int kk = k8 * 8 + (lane & 3);
#pragma unroll
            for (int mi = 0; mi < 2; mi++) {
                int r = wm * 32 + mi * 16 + (lane >> 2);
                afr[mi][0] = f2tf32(As[r    ][kk    ]);
                afr[mi][1] = f2tf32(As[r + 8][kk    ]);
                afr[mi][2] = f2tf32(As[r    ][kk + 4]);
                afr[mi][3] = f2tf32(As[r + 8][kk + 4]);
            }
#pragma unroll
            for (int ni = 0; ni < 8; ni++) {
                int n = wn * 64 + ni * 8 + (lane >> 2);
                bfr[ni][0] = f2tf32(Bs[n][kk    ]);
                bfr[ni][1] = f2tf32(Bs[n][kk + 4]);
            }
#pragma unroll
            for (int mi = 0; mi < 2; mi++)
#pragma unroll
                for (int ni = 0; ni < 8; ni++)
                    mma_tf32(acc[mi][ni], afr[mi], bfr[ni]);
        }
        __syncthreads();
    }

    // Epilogue
#pragma unroll
    for (int mi = 0; mi < 2; mi++) {
#pragma unroll
        for (int ni = 0; ni < 8; ni++) {
            int r0 = m0 + wm * 32 + mi * 16 + (lane >> 2);
            int c0 = n0 + wn * 64 + ni * 8 + (lane & 3) * 2;
#pragma unroll
            for (int e = 0; e < 4; e++) {
                int m = r0 + ((e >= 2) ? 8 : 0);
                int n = c0 + (e & 1);
                float v = acc[mi][ni][e] + bz[n];
                if (MODE == 0) {
                    int b = m >> 12;           // /4096
                    int l = m & 4095;
                    int w = l >> 7, rr = l & 127;
                    int h = n >> 6, d = n & 63;
                    size_t idx = ((((size_t)((b * NW + w) * NHEAD + h)) * WIN + rr) * HDIM) + d;
                    g_qkv[(size_t)z * QKV_STRIDE + idx] = v;
                } else {
                    Yp[(size_t)m * D_MODEL + n] = v;
                }
            }
        }
    }
}

// ---------------------------------------------------------------------------
// Windowed attention: one CTA per (b, w, h). Tiles are contiguous 128x64 fp32.
// SMEM: q[128][68] k[128][68] v[128][68] s[128][132] sum[128]  (~171 KB)
// ---------------------------------------------------------------------------
#define QLD 68
#define SLD 132
#define ATTN_SMEM ((3 * 128 * QLD + 128 * SLD + 128) * 4)

__global__ __launch_bounds__(256) void attn_kernel() {
    extern __shared__ float sm[];
    float* sq = sm;
    float* sk = sq + 128 * QLD;
    float* sv = sk + 128 * QLD;
    float* sp = sv + 128 * QLD;
    float* ssum = sp + 128 * SLD;

    const int bid = blockIdx.x;
    const int h = bid & 15;
    const int w = (bid >> 4) & 31;
    const int b = bid >> 9;
    const size_t tile = ((size_t)((b * NW + w) * NHEAD + h)) * (WIN * HDIM);

    const float* gq = g_qkv + tile;
    const float* gk = g_qkv + QKV_STRIDE + tile;
    const float* gv = g_qkv + 2 * QKV_STRIDE + tile;

    const int tid = threadIdx.x;

    // Load q,k,v tiles (128x64 each), float4, padded rows
#pragma unroll
    for (int i = 0; i < 8; i++) {
        int idx = tid + i * 256;          // 0..2047 float4 slots
        int r = idx >> 4;                 // /16
        int c = (idx & 15) * 4;
        *(float4*)&sq[r * QLD + c] = *(const float4*)&gq[r * HDIM + c];
        *(float4*)&sk[r * QLD + c] = *(const float4*)&gk[r * HDIM + c];
        *(float4*)&sv[r * QLD + c] = *(const float4*)&gv[r * HDIM + c];
    }
    __syncthreads();

    // Phase B: scores. thread t -> row r = t/2, j-half = (t&1)*64
    {
        const int r = tid >> 1;
        const int jbase = (tid & 1) * 64;
        float qr[64];
#pragma unroll
        for (int d4 = 0; d4 < 16; d4++) {
            float4 t4 = *(const float4*)&sq[r * QLD + d4 * 4];
            qr[4 * d4] = t4.x; qr[4 * d4 + 1] = t4.y; qr[4 * d4 + 2] = t4.z; qr[4 * d4 + 3] = t4.w;
        }
        const float scale = 0.125f;  // 1/sqrt(64)
        for (int jj = 0; jj < 64; jj++) {
            int j = jbase + jj;
            float s = 0.f;
#pragma unroll
            for (int d4 = 0; d4 < 16; d4++) {
                float4 k4 = *(const float4*)&sk[j * QLD + d4 * 4];
                s += qr[4 * d4] * k4.x + qr[4 * d4 + 1] * k4.y
                   + qr[4 * d4 + 2] * k4.z + qr[4 * d4 + 3] * k4.w;
            }
            sp[r * SLD + j] = s * scale;
        }
    }
    __syncthreads();

    // Phase C: softmax (threads 0..127, one row each). Store un-normalized e,
    // row sums to ssum; 1/sum folded into output.
    if (tid < 128) {
        const int r = tid;
        float mx = -1e30f;
#pragma unroll 4
        for (int j = 0; j < 128; j++) mx = fmaxf(mx, sp[r * SLD + j]);
        float sum = 0.f;
#pragma unroll 4
        for (int j = 0; j < 128; j++) {
            float e = __expf(sp[r * SLD + j] - mx);
            sp[r * SLD + j] = e;
            sum += e;
        }
        ssum[r] = sum;
    }
    __syncthreads();

    // Phase D: O = P @ V. thread t -> row r = t&127, d-half dh = (t>>7)*32
    {
        const int r = tid & 127;
        const int dh = (tid >> 7) * 32;
        float o[32];
#pragma unroll
        for (int d = 0; d < 32; d++) o[d] = 0.f;
        for (int j = 0; j < 128; j++) {
            float p = sp[r * SLD + j];
#pragma unroll
            for (int d4 = 0; d4 < 8; d4++) {
                float4 v4 = *(const float4*)&sv[j * QLD + dh + d4 * 4];
                o[4 * d4] += p * v4.x; o[4 * d4 + 1] += p * v4.y;
                o[4 * d4 + 2] += p * v4.z; o[4 * d4 + 3] += p * v4.w;
            }
        }
        float inv = 1.f / ssum[r];
        size_t ob = ((size_t)b * SEQ + (size_t)w * WIN + r) * D_MODEL + h * HDIM + dh;
#pragma unroll
        for (int d = 0; d < 32; d += 4) {
            float4 w4 = make_float4(o[d] * inv, o[d + 1] * inv, o[d + 2] * inv, o[d + 3] * inv);
            *(float4*)&g_attn[ob + d] = w4;
        }
    }
}

// ---------------------------------------------------------------------------
extern "C" void kernel_launch(void* const* d_in, const int* in_sizes, int n_in,
                              void* d_out, int out_size) {
    const float* q   = (const float*)d_in[0];
    const float* k   = (const float*)d_in[1];
    const float* v   = (const float*)d_in[2];
    const float* ipw = (const float*)d_in[3];
    const float* ipb = (const float*)d_in[4];
    const float* ow  = (const float*)d_in[5];
    const float* ob  = (const float*)d_in[6];
    float* out = (float*)d_out;

    cudaFuncSetAttribute(attn_kernel, cudaFuncAttributeMaxDynamicSharedMemorySize, ATTN_SMEM);

    // 1) QKV projection: grid (N/128, M/128, 3)
    dim3 g0(D_MODEL / BN, M_TOTAL / BM, 3);
    gemm_tn<0><<<g0, 256>>>(q, k, v, ipw, ipb, nullptr);

    // 2) Windowed attention: 2048 blocks
    attn_kernel<<<BATCH * NW * NHEAD, 256, ATTN_SMEM>>>();

    // 3) Output projection
    dim3 g1(D_MODEL / BN, M_TOTAL / BM, 1);
    gemm_tn<1><<<g1, 256>>>(nullptr, nullptr, nullptr, ow, ob, out);
}

// round 2
// speedup vs baseline: 1.1388x; 1.1388x over previous
#include <cuda_runtime.h>
#include <cstdint>
#include <cstdio>

#define D_MODEL 1024
#define NHEAD   16
#define HDIM    64
#define WIN     128
#define BATCH   4
#define SEQ     4096
#define NW      (SEQ / WIN)            // 32
#define M_TOTAL (BATCH * SEQ)          // 16384
#define QKV_STRIDE ((size_t)M_TOTAL * D_MODEL)  // 16777216

// Scratch (allocation-free rule: device globals)
__device__ float g_qkv[3ull * M_TOTAL * D_MODEL];   // [z][b][w][h][row][d] tiles
__device__ float g_attn[(size_t)M_TOTAL * D_MODEL]; // [b][l][h*64+d] row-major

// ---------------------------------------------------------------------------
// TF32 helpers
// ---------------------------------------------------------------------------
__device__ __forceinline__ uint32_t f2tf32(float f) {
    uint32_t u;
    asm("cvt.rna.tf32.f32 %0, %1;" : "=r"(u) : "f"(f));
    return u;
}

__device__ __forceinline__ void mma_tf32(float c[4], const uint32_t a[4], const uint32_t b[2]) {
    asm volatile(
        "mma.sync.aligned.m16n8k8.row.col.f32.tf32.tf32.f32 "
        "{%0,%1,%2,%3}, {%4,%5,%6,%7}, {%8,%9}, {%0,%1,%2,%3};\n"
        : "+f"(c[0]), "+f"(c[1]), "+f"(c[2]), "+f"(c[3])
        : "r"(a[0]), "r"(a[1]), "r"(a[2]), "r"(a[3]), "r"(b[0]), "r"(b[1]));
}

__device__ __forceinline__ void ldsm_x4(uint32_t& r0, uint32_t& r1, uint32_t& r2, uint32_t& r3,
                                        uint32_t saddr) {
    asm volatile("ldmatrix.sync.aligned.m8n8.x4.shared.b16 {%0,%1,%2,%3}, [%4];"
                 : "=r"(r0), "=r"(r1), "=r"(r2), "=r"(r3) : "r"(saddr));
}

// ---------------------------------------------------------------------------
// GEMM: Y[M,N] = X[M,K] @ W[N,K]^T + bias   (TN, both K-contiguous)
// smem holds TF32-converted operands; fragments loaded via ldmatrix.x4.
// Block tile 128x128, BK=32, 256 threads (8 warps as 4x2, warp tile 32x64).
// ---------------------------------------------------------------------------
#define BM 128
#define BN 128
#define BK 32
#define LDAB 36   // u32 pitch: 144B, 16B-aligned, 4-bank row step -> LDSM conflict-free

template <int MODE>
__global__ __launch_bounds__(256) void gemm_tn(
    const float* __restrict__ Xq, const float* __restrict__ Xk, const float* __restrict__ Xv,
    const float* __restrict__ Wp, const float* __restrict__ bp, float* __restrict__ Yp)
{
    __shared__ uint32_t As[BM][LDAB];
    __shared__ uint32_t Bs[BN][LDAB];

    const int z = blockIdx.z;
    const float* X;
    const float* Wz;
    const float* bz;
    if (MODE == 0) {
        X  = (z == 0) ? Xq : (z == 1) ? Xk : Xv;
        Wz = Wp + (size_t)z * D_MODEL * D_MODEL;
        bz = bp + z * D_MODEL;
    } else {
        X  = g_attn;
        Wz = Wp;
        bz = bp;
    }

    const int m0 = blockIdx.y * BM;
    const int n0 = blockIdx.x * BN;
    const int tid  = threadIdx.x;
    const int warp = tid >> 5, lane = tid & 31;
    const int wm = warp >> 1, wn = warp & 1;   // 4x2 warps

    float acc[2][8][4];
#pragma unroll
    for (int mi = 0; mi < 2; mi++)
#pragma unroll
        for (int ni = 0; ni < 8; ni++)
#pragma unroll
            for (int r = 0; r < 4; r++) acc[mi][ni][r] = 0.f;

    // staging coordinates: each thread loads 4 float4 per matrix per ktile
    const int lrow = tid >> 3;          // 0..31 (plus i*32)
    const int lcol = (tid & 7) * 4;     // 0..28 step 4

    // LDSM lane addressing (lane-dependent parts, in bytes)
    const uint32_t sA = (uint32_t)__cvta_generic_to_shared(&As[0][0]);
    const uint32_t sB = (uint32_t)__cvta_generic_to_shared(&Bs[0][0]);
    // A: row = wm*32 + mi*16 + (lane&15), col = k8*8 + (lane>>4)*4
    const uint32_t aRow = wm * 32 + (lane & 15);
    const uint32_t aCol = (lane >> 4) * 4;
    // B: row = wn*64 + p*16 + ((lane>>4)<<3) + (lane&7), col = k8*8 + ((lane>>3)&1)*4
    const uint32_t bRow = wn * 64 + ((lane >> 4) << 3) + (lane & 7);
    const uint32_t bCol = ((lane >> 3) & 1) * 4;

    // -------- prefetch tile 0 --------
    float4 pa[4], pb[4];
#pragma unroll
    for (int i = 0; i < 4; i++) {
        int r = lrow + i * 32;
        pa[i] = *(const float4*)&X [(size_t)(m0 + r) * D_MODEL + lcol];
        pb[i] = *(const float4*)&Wz[(size_t)(n0 + r) * D_MODEL + lcol];
    }

    for (int kt = 0; kt < D_MODEL; kt += BK) {
        // store staged tile (convert to tf32 once here)
#pragma unroll
        for (int i = 0; i < 4; i++) {
            int r = lrow + i * 32;
            uint4 ac = make_uint4(f2tf32(pa[i].x), f2tf32(pa[i].y), f2tf32(pa[i].z), f2tf32(pa[i].w));
            *(uint4*)&As[r][lcol] = ac;
            uint4 bc = make_uint4(f2tf32(pb[i].x), f2tf32(pb[i].y), f2tf32(pb[i].z), f2tf32(pb[i].w));
            *(uint4*)&Bs[r][lcol] = bc;
        }
        __syncthreads();

        // prefetch next tile while computing this one
        if (kt + BK < D_MODEL) {
#pragma unroll
            for (int i = 0; i < 4; i++) {
                int r = lrow + i * 32;
                pa[i] = *(const float4*)&X [(size_t)(m0 + r) * D_MODEL + kt + BK + lcol];
                pb[i] = *(const float4*)&Wz[(size_t)(n0 + r) * D_MODEL + kt + BK + lcol];
            }
        }

#pragma unroll
        for (int k8 = 0; k8 < 4; k8++) {
            uint32_t afr[2][4];
            uint32_t bfr[8][2];
#pragma unroll
            for (int mi = 0; mi < 2; mi++) {
                uint32_t addr = sA + (((aRow + mi * 16) * LDAB) + k8 * 8 + aCol) * 4;
                ldsm_x4(afr[mi][0], afr[mi][1], afr[mi][2], afr[mi][3], addr);
            }
#pragma unroll
            for (int p = 0; p < 4; p++) {
                uint32_t addr = sB + (((bRow + p * 16) * LDAB) + k8 * 8 + bCol) * 4;
                ldsm_x4(bfr[2 * p][0], bfr[2 * p][1], bfr[2 * p + 1][0], bfr[2 * p + 1][1], addr);
            }
#pragma unroll
            for (int mi = 0; mi < 2; mi++)
#pragma unroll
                for (int ni = 0; ni < 8; ni++)
                    mma_tf32(acc[mi][ni], afr[mi], bfr[ni]);
        }
        __syncthreads();
    }

    // Epilogue
#pragma unroll
    for (int mi = 0; mi < 2; mi++) {
#pragma unroll
        for (int ni = 0; ni < 8; ni++) {
            int r0 = m0 + wm * 32 + mi * 16 + (lane >> 2);
            int c0 = n0 + wn * 64 + ni * 8 + (lane & 3) * 2;
#pragma unroll
            for (int e = 0; e < 4; e++) {
                int m = r0 + ((e >= 2) ? 8 : 0);
                int n = c0 + (e & 1);
                float v = acc[mi][ni][e] + bz[n];
                if (MODE == 0) {
                    int b = m >> 12;           // /4096
                    int l = m & 4095;
                    int w = l >> 7, rr = l & 127;
                    int h = n >> 6, d = n & 63;
                    size_t idx = ((((size_t)((b * NW + w) * NHEAD + h)) * WIN + rr) * HDIM) + d;
                    g_qkv[(size_t)z * QKV_STRIDE + idx] = v;
                } else {
                    Yp[(size_t)m * D_MODEL + n] = v;
                }
            }
        }
    }
}

// ---------------------------------------------------------------------------
// Windowed attention: one CTA per (b, w, h). Tiles are contiguous 128x64 fp32.
// SMEM: q[128][68] k[128][68] v[128][68] s[128][132] sum[128]  (~171 KB)
// ---------------------------------------------------------------------------
#define QLD 68
#define SLD 132
#define ATTN_SMEM ((3 * 128 * QLD + 128 * SLD + 128) * 4)

__global__ __launch_bounds__(256) void attn_kernel() {
    extern __shared__ float sm[];
    float* sq = sm;
    float* sk = sq + 128 * QLD;
    float* sv = sk + 128 * QLD;
    float* sp = sv + 128 * QLD;
    float* ssum = sp + 128 * SLD;

    const int bid = blockIdx.x;
    const int h = bid & 15;
    const int w = (bid >> 4) & 31;
    const int b = bid >> 9;
    const size_t tile = ((size_t)((b * NW + w) * NHEAD + h)) * (WIN * HDIM);

    const float* gq = g_qkv + tile;
    const float* gk = g_qkv + QKV_STRIDE + tile;
    const float* gv = g_qkv + 2 * QKV_STRIDE + tile;

    const int tid = threadIdx.x;

    // Load q,k,v tiles (128x64 each), float4, padded rows
#pragma unroll
    for (int i = 0; i < 8; i++) {
        int idx = tid + i * 256;          // 0..2047 float4 slots
        int r = idx >> 4;                 // /16
        int c = (idx & 15) * 4;
        *(float4*)&sq[r * QLD + c] = *(const float4*)&gq[r * HDIM + c];
        *(float4*)&sk[r * QLD + c] = *(const float4*)&gk[r * HDIM + c];
        *(float4*)&sv[r * QLD + c] = *(const float4*)&gv[r * HDIM + c];
    }
    __syncthreads();

    // Phase B: scores. thread t -> row r = t/2, j-half = (t&1)*64
    {
        const int r = tid >> 1;
        const int jbase = (tid & 1) * 64;
        float qr[64];
#pragma unroll
        for (int d4 = 0; d4 < 16; d4++) {
            float4 t4 = *(const float4*)&sq[r * QLD + d4 * 4];
            qr[4 * d4] = t4.x; qr[4 * d4 + 1] = t4.y; qr[4 * d4 + 2] = t4.z; qr[4 * d4 + 3] = t4.w;
        }
        const float scale = 0.125f;  // 1/sqrt(64)
        for (int jj = 0; jj < 64; jj++) {
            int j = jbase + jj;
            float s = 0.f;
#pragma unroll
            for (int d4 = 0; d4 < 16; d4++) {
                float4 k4 = *(const float4*)&sk[j * QLD + d4 * 4];
                s += qr[4 * d4] * k4.x + qr[4 * d4 + 1] * k4.y
                   + qr[4 * d4 + 2] * k4.z + qr[4 * d4 + 3] * k4.w;
            }
            sp[r * SLD + j] = s * scale;
        }
    }
    __syncthreads();

    // Phase C: softmax (threads 0..127, one row each). Store un-normalized e,
    // row sums to ssum; 1/sum folded into output.
    if (tid < 128) {
        const int r = tid;
        float mx = -1e30f;
#pragma unroll 4
        for (int j = 0; j < 128; j++) mx = fmaxf(mx, sp[r * SLD + j]);
        float sum = 0.f;
#pragma unroll 4
        for (int j = 0; j < 128; j++) {
            float e = __expf(sp[r * SLD + j] - mx);
            sp[r * SLD + j] = e;
            sum += e;
        }
        ssum[r] = sum;
    }
    __syncthreads();

    // Phase D: O = P @ V. thread t -> row r = t&127, d-half dh = (t>>7)*32
    {
        const int r = tid & 127;
        const int dh = (tid >> 7) * 32;
        float o[32];
#pragma unroll
        for (int d = 0; d < 32; d++) o[d] = 0.f;
        for (int j = 0; j < 128; j++) {
            float p = sp[r * SLD + j];
#pragma unroll
            for (int d4 = 0; d4 < 8; d4++) {
                float4 v4 = *(const float4*)&sv[j * QLD + dh + d4 * 4];
                o[4 * d4] += p * v4.x; o[4 * d4 + 1] += p * v4.y;
                o[4 * d4 + 2] += p * v4.z; o[4 * d4 + 3] += p * v4.w;
            }
        }
        float inv = 1.f / ssum[r];
        size_t ob = ((size_t)b * SEQ + (size_t)w * WIN + r) * D_MODEL + h * HDIM + dh;
#pragma unroll
        for (int d = 0; d < 32; d += 4) {
            float4 w4 = make_float4(o[d] * inv, o[d + 1] * inv, o[d + 2] * inv, o[d + 3] * inv);
            *(float4*)&g_attn[ob + d] = w4;
        }
    }
}

// ---------------------------------------------------------------------------
extern "C" void kernel_launch(void* const* d_in, const int* in_sizes, int n_in,
                              void* d_out, int out_size) {
    const float* q   = (const float*)d_in[0];
    const float* k   = (const float*)d_in[1];
    const float* v   = (const float*)d_in[2];
    const float* ipw = (const float*)d_in[3];
    const float* ipb = (const float*)d_in[4];
    const float* ow  = (const float*)d_in[5];
    const float* ob  = (const float*)d_in[6];
    float* out = (float*)d_out;

    cudaFuncSetAttribute(attn_kernel, cudaFuncAttributeMaxDynamicSharedMemorySize, ATTN_SMEM);

    // 1) QKV projection: grid (N/128, M/128, 3)
    dim3 g0(D_MODEL / BN, M_TOTAL / BM, 3);
    gemm_tn<0><<<g0, 256>>>(q, k, v, ipw, ipb, nullptr);

    // 2) Windowed attention: 2048 blocks
    attn_kernel<<<BATCH * NW * NHEAD, 256, ATTN_SMEM>>>();

    // 3) Output projection
    dim3 g1(D_MODEL / BN, M_TOTAL / BM, 1);
    gemm_tn<1><<<g1, 256>>>(nullptr, nullptr, nullptr, ow, ob, out);
}

// round 3
// speedup vs baseline: 1.2130x; 1.0652x over previous
#include <cuda_runtime.h>
#include <cstdint>
#include <cstdio>

#define D_MODEL 1024
#define NHEAD   16
#define HDIM    64
#define WIN     128
#define BATCH   4
#define SEQ     4096
#define NW      (SEQ / WIN)            // 32
#define M_TOTAL (BATCH * SEQ)          // 16384
#define QKV_STRIDE ((size_t)M_TOTAL * D_MODEL)  // 16777216

// Scratch (allocation-free rule: device globals)
__device__ float g_qkv[3ull * M_TOTAL * D_MODEL];   // [z][b][w][h][row][d] tiles
__device__ float g_attn[(size_t)M_TOTAL * D_MODEL]; // [b][l][h*64+d] row-major

// ---------------------------------------------------------------------------
// TF32 / MMA / async helpers
// ---------------------------------------------------------------------------
__device__ __forceinline__ uint32_t f2tf32(float f) {
    uint32_t u;
    asm("cvt.rna.tf32.f32 %0, %1;" : "=r"(u) : "f"(f));
    return u;
}
__device__ __forceinline__ uint32_t u2tf32(uint32_t x) {
    return f2tf32(__uint_as_float(x));
}

__device__ __forceinline__ void mma_tf32(float c[4], const uint32_t a[4], const uint32_t b[2]) {
    asm volatile(
        "mma.sync.aligned.m16n8k8.row.col.f32.tf32.tf32.f32 "
        "{%0,%1,%2,%3}, {%4,%5,%6,%7}, {%8,%9}, {%0,%1,%2,%3};\n"
        : "+f"(c[0]), "+f"(c[1]), "+f"(c[2]), "+f"(c[3])
        : "r"(a[0]), "r"(a[1]), "r"(a[2]), "r"(a[3]), "r"(b[0]), "r"(b[1]));
}

__device__ __forceinline__ void ldsm_x4(uint32_t& r0, uint32_t& r1, uint32_t& r2, uint32_t& r3,
                                        uint32_t saddr) {
    asm volatile("ldmatrix.sync.aligned.m8n8.x4.shared.b16 {%0,%1,%2,%3}, [%4];"
                 : "=r"(r0), "=r"(r1), "=r"(r2), "=r"(r3) : "r"(saddr));
}

__device__ __forceinline__ void cp_async16(uint32_t dst, const void* src) {
    asm volatile("cp.async.cg.shared.global [%0], [%1], 16;\n" :: "r"(dst), "l"(src));
}
__device__ __forceinline__ void cp_commit() { asm volatile("cp.async.commit_group;\n" ::: "memory"); }
template <int N>
__device__ __forceinline__ void cp_wait() { asm volatile("cp.async.wait_group %0;\n" :: "n"(N) : "memory"); }

// ---------------------------------------------------------------------------
// GEMM: Y[M,N] = X[M,K] @ W[N,K]^T + bias   (TN, both K-contiguous)
// 512 threads, 16 warps (4x4), warp tile 32x32, block tile 128x128, BK=32.
// 3-stage cp.async pipeline; smem holds raw fp32; tf32 cvt on fragments.
// ---------------------------------------------------------------------------
#define BM 128
#define BN 128
#define BK 32
#define LDAB 36          // u32 pitch: 144B, LDSM conflict-free
#define STAGES 3
#define SSZ (2 * 128 * LDAB)                 // u32 per stage (A then B)
#define GEMM_SMEM (STAGES * SSZ * 4)         // 110592 bytes

template <int MODE>
__global__ __launch_bounds__(512) void gemm_tn(
    const float* __restrict__ Xq, const float* __restrict__ Xk, const float* __restrict__ Xv,
    const float* __restrict__ Wp, const float* __restrict__ bp, float* __restrict__ Yp)
{
    extern __shared__ uint32_t smem_u[];
    const uint32_t smem_base = (uint32_t)__cvta_generic_to_shared(smem_u);

    const int z = blockIdx.z;
    const float* X;
    const float* Wz;
    const float* bz;
    if (MODE == 0) {
        X  = (z == 0) ? Xq : (z == 1) ? Xk : Xv;
        Wz = Wp + (size_t)z * D_MODEL * D_MODEL;
        bz = bp + z * D_MODEL;
    } else {
        X  = g_attn;
        Wz = Wp;
        bz = bp;
    }

    const int m0 = blockIdx.y * BM;
    const int n0 = blockIdx.x * BN;
    const int tid  = threadIdx.x;
    const int warp = tid >> 5, lane = tid & 31;
    const int wm = warp >> 2, wn = warp & 3;   // 4x4 warps, warp tile 32x32

    float acc[2][4][4];
#pragma unroll
    for (int mi = 0; mi < 2; mi++)
#pragma unroll
        for (int ni = 0; ni < 4; ni++)
#pragma unroll
            for (int r = 0; r < 4; r++) acc[mi][ni][r] = 0.f;

    // staging: each thread cp.asyncs 2 float4 per matrix per ktile
    const int lrow = tid >> 3;          // 0..63 (plus 64)
    const int lcol = (tid & 7) * 4;     // 0..28 step 4

    // LDSM lane addressing (verified layout from R1/R2)
    const uint32_t aRow = (lane & 15);
    const uint32_t aCol = (lane >> 4) * 4;
    const uint32_t bRow = ((lane >> 4) << 3) + (lane & 7);
    const uint32_t bCol = ((lane >> 3) & 1) * 4;

    auto issue_stage = [&](int s, int kt) {
        const uint32_t sa = smem_base + (uint32_t)s * SSZ * 4;
        const uint32_t sb = sa + 128 * LDAB * 4;
#pragma unroll
        for (int i = 0; i < 2; i++) {
            const int r = lrow + i * 64;
            cp_async16(sa + (r * LDAB + lcol) * 4, &X [(size_t)(m0 + r) * D_MODEL + kt + lcol]);
            cp_async16(sb + (r * LDAB + lcol) * 4, &Wz[(size_t)(n0 + r) * D_MODEL + kt + lcol]);
        }
    };

    int kt_load = 0;
#pragma unroll
    for (int s = 0; s < STAGES - 1; s++) {
        issue_stage(s, kt_load);
        cp_commit();
        kt_load += BK;
    }

    int sc = 0;
    for (int kt = 0; kt < D_MODEL; kt += BK) {
        cp_wait<STAGES - 2>();
        __syncthreads();

        if (kt_load < D_MODEL) {
            int sl = sc + STAGES - 1; if (sl >= STAGES) sl -= STAGES;
            issue_stage(sl, kt_load);
            kt_load += BK;
        }
        cp_commit();

        const uint32_t sA = smem_base + (uint32_t)sc * SSZ * 4;
        const uint32_t sB = sA + 128 * LDAB * 4;

#pragma unroll
        for (int k8 = 0; k8 < 4; k8++) {
            uint32_t afr[2][4];
            uint32_t bfr[4][2];
#pragma unroll
            for (int mi = 0; mi < 2; mi++) {
                uint32_t addr = sA + (((wm * 32 + mi * 16 + aRow) * LDAB) + k8 * 8 + aCol) * 4;
                ldsm_x4(afr[mi][0], afr[mi][1], afr[mi][2], afr[mi][3], addr);
            }
#pragma unroll
            for (int p = 0; p < 2; p++) {
                uint32_t addr = sB + (((wn * 32 + p * 16 + bRow) * LDAB) + k8 * 8 + bCol) * 4;
                ldsm_x4(bfr[2 * p][0], bfr[2 * p][1], bfr[2 * p + 1][0], bfr[2 * p + 1][1], addr);
            }
            // convert fragments fp32 -> tf32
#pragma unroll
            for (int mi = 0; mi < 2; mi++)
#pragma unroll
                for (int r = 0; r < 4; r++) afr[mi][r] = u2tf32(afr[mi][r]);
#pragma unroll
            for (int ni = 0; ni < 4; ni++) {
                bfr[ni][0] = u2tf32(bfr[ni][0]);
                bfr[ni][1] = u2tf32(bfr[ni][1]);
            }
#pragma unroll
            for (int mi = 0; mi < 2; mi++)
#pragma unroll
                for (int ni = 0; ni < 4; ni++)
                    mma_tf32(acc[mi][ni], afr[mi], bfr[ni]);
        }
        sc++; if (sc == STAGES) sc = 0;
        __syncthreads();
    }

    // Epilogue
#pragma unroll
    for (int mi = 0; mi < 2; mi++) {
#pragma unroll
        for (int ni = 0; ni < 4; ni++) {
            int r0 = m0 + wm * 32 + mi * 16 + (lane >> 2);
            int c0 = n0 + wn * 32 + ni * 8 + (lane & 3) * 2;
#pragma unroll
            for (int e = 0; e < 4; e++) {
                int m = r0 + ((e >= 2) ? 8 : 0);
                int n = c0 + (e & 1);
                float v = acc[mi][ni][e] + bz[n];
                if (MODE == 0) {
                    int b = m >> 12;           // /4096
                    int l = m & 4095;
                    int w = l >> 7, rr = l & 127;
                    int h = n >> 6, d = n & 63;
                    size_t idx = ((((size_t)((b * NW + w) * NHEAD + h)) * WIN + rr) * HDIM) + d;
                    g_qkv[(size_t)z * QKV_STRIDE + idx] = v;
                } else {
                    Yp[(size_t)m * D_MODEL + n] = v;
                }
            }
        }
    }
}

// ---------------------------------------------------------------------------
// Windowed attention: one CTA per (b, w, h). Tiles are contiguous 128x64 fp32.
// SMEM: q[128][68] k[128][68] v[128][68] s[128][132] sum[128]  (~171 KB)
// ---------------------------------------------------------------------------
#define QLD 68
#define SLD 132
#define ATTN_SMEM ((3 * 128 * QLD + 128 * SLD + 128) * 4)

__global__ __launch_bounds__(256) void attn_kernel() {
    extern __shared__ float sm[];
    float* sq = sm;
    float* sk = sq + 128 * QLD;
    float* sv = sk + 128 * QLD;
    float* sp = sv + 128 * QLD;
    float* ssum = sp + 128 * SLD;

    const int bid = blockIdx.x;
    const int h = bid & 15;
    const int w = (bid >> 4) & 31;
    const int b = bid >> 9;
    const size_t tile = ((size_t)((b * NW + w) * NHEAD + h)) * (WIN * HDIM);

    const float* gq = g_qkv + tile;
    const float* gk = g_qkv + QKV_STRIDE + tile;
    const float* gv = g_qkv + 2 * QKV_STRIDE + tile;

    const int tid = threadIdx.x;

    // Load q,k,v tiles (128x64 each), float4, padded rows
#pragma unroll
    for (int i = 0; i < 8; i++) {
        int idx = tid + i * 256;          // 0..2047 float4 slots
        int r = idx >> 4;                 // /16
        int c = (idx & 15) * 4;
        *(float4*)&sq[r * QLD + c] = *(const float4*)&gq[r * HDIM + c];
        *(float4*)&sk[r * QLD + c] = *(const float4*)&gk[r * HDIM + c];
        *(float4*)&sv[r * QLD + c] = *(const float4*)&gv[r * HDIM + c];
    }
    __syncthreads();

    // Phase B: scores. thread t -> row r = t/2, j-half = (t&1)*64
    {
        const int r = tid >> 1;
        const int jbase = (tid & 1) * 64;
        float qr[64];
#pragma unroll
        for (int d4 = 0; d4 < 16; d4++) {
            float4 t4 = *(const float4*)&sq[r * QLD + d4 * 4];
            qr[4 * d4] = t4.x; qr[4 * d4 + 1] = t4.y; qr[4 * d4 + 2] = t4.z; qr[4 * d4 + 3] = t4.w;
        }
        const float scale = 0.125f;  // 1/sqrt(64)
        for (int jj = 0; jj < 64; jj++) {
            int j = jbase + jj;
            float s = 0.f;
#pragma unroll
            for (int d4 = 0; d4 < 16; d4++) {
                float4 k4 = *(const float4*)&sk[j * QLD + d4 * 4];
                s += qr[4 * d4] * k4.x + qr[4 * d4 + 1] * k4.y
                   + qr[4 * d4 + 2] * k4.z + qr[4 * d4 + 3] * k4.w;
            }
            sp[r * SLD + j] = s * scale;
        }
    }
    __syncthreads();

    // Phase C: softmax (threads 0..127, one row each). Store un-normalized e,
    // row sums to ssum; 1/sum folded into output.
    if (tid < 128) {
        const int r = tid;
        float mx = -1e30f;
#pragma unroll 4
        for (int j = 0; j < 128; j++) mx = fmaxf(mx, sp[r * SLD + j]);
        float sum = 0.f;
#pragma unroll 4
        for (int j = 0; j < 128; j++) {
            float e = __expf(sp[r * SLD + j] - mx);
            sp[r * SLD + j] = e;
            sum += e;
        }
        ssum[r] = sum;
    }
    __syncthreads();

    // Phase D: O = P @ V. thread t -> row r = t&127, d-half dh = (t>>7)*32
    {
        const int r = tid & 127;
        const int dh = (tid >> 7) * 32;
        float o[32];
#pragma unroll
        for (int d = 0; d < 32; d++) o[d] = 0.f;
        for (int j = 0; j < 128; j++) {
            float p = sp[r * SLD + j];
#pragma unroll
            for (int d4 = 0; d4 < 8; d4++) {
                float4 v4 = *(const float4*)&sv[j * QLD + dh + d4 * 4];
                o[4 * d4] += p * v4.x; o[4 * d4 + 1] += p * v4.y;
                o[4 * d4 + 2] += p * v4.z; o[4 * d4 + 3] += p * v4.w;
            }
        }
        float inv = 1.f / ssum[r];
        size_t ob = ((size_t)b * SEQ + (size_t)w * WIN + r) * D_MODEL + h * HDIM + dh;
#pragma unroll
        for (int d = 0; d < 32; d += 4) {
            float4 w4 = make_float4(o[d] * inv, o[d + 1] * inv, o[d + 2] * inv, o[d + 3] * inv);
            *(float4*)&g_attn[ob + d] = w4;
        }
    }
}

// ---------------------------------------------------------------------------
extern "C" void kernel_launch(void* const* d_in, const int* in_sizes, int n_in,
                              void* d_out, int out_size) {
    const float* q   = (const float*)d_in[0];
    const float* k   = (const float*)d_in[1];
    const float* v   = (const float*)d_in[2];
    const float* ipw = (const float*)d_in[3];
    const float* ipb = (const float*)d_in[4];
    const float* ow  = (const float*)d_in[5];
    const float* ob  = (const float*)d_in[6];
    float* out = (float*)d_out;

    cudaFuncSetAttribute(gemm_tn<0>, cudaFuncAttributeMaxDynamicSharedMemorySize, GEMM_SMEM);
    cudaFuncSetAttribute(gemm_tn<1>, cudaFuncAttributeMaxDynamicSharedMemorySize, GEMM_SMEM);
    cudaFuncSetAttribute(attn_kernel, cudaFuncAttributeMaxDynamicSharedMemorySize, ATTN_SMEM);

    // 1) QKV projection: grid (N/128, M/128, 3)
    dim3 g0(D_MODEL / BN, M_TOTAL / BM, 3);
    gemm_tn<0><<<g0, 512, GEMM_SMEM>>>(q, k, v, ipw, ipb, nullptr);

    // 2) Windowed attention: 2048 blocks
    attn_kernel<<<BATCH * NW * NHEAD, 256, ATTN_SMEM>>>();

    // 3) Output projection
    dim3 g1(D_MODEL / BN, M_TOTAL / BM, 1);
    gemm_tn<1><<<g1, 512, GEMM_SMEM>>>(nullptr, nullptr, nullptr, ow, ob, out);
}

// round 6
// speedup vs baseline: 1.6566x; 1.3657x over previous
#include <cuda_runtime.h>
#include <cstdint>
#include <cstdio>

#define D_MODEL 1024
#define NHEAD   16
#define HDIM    64
#define WIN     128
#define BATCH   4
#define SEQ     4096
#define NW      (SEQ / WIN)            // 32
#define M_TOTAL (BATCH * SEQ)          // 16384
#define QKV_STRIDE ((size_t)M_TOTAL * D_MODEL)  // 16777216

// Scratch (allocation-free rule: device globals)
__device__ float g_qkv[3ull * M_TOTAL * D_MODEL];   // [z][b][w][h][row][d] tiles
__device__ float g_attn[(size_t)M_TOTAL * D_MODEL]; // [b][l][h*64+d] row-major

// ---------------------------------------------------------------------------
// TF32 / MMA / async helpers (generic-target ISA only; tcgen05 unavailable
// because the harness ptxas targets sm_103 without the 'a' feature)
// ---------------------------------------------------------------------------
__device__ __forceinline__ uint32_t f2tf32(float f) {
    uint32_t u;
    asm("cvt.rna.tf32.f32 %0, %1;" : "=r"(u) : "f"(f));
    return u;
}
__device__ __forceinline__ uint32_t u2tf32(uint32_t x) {
    return f2tf32(__uint_as_float(x));
}

__device__ __forceinline__ void mma_tf32(float c[4], const uint32_t a[4], const uint32_t b[2]) {
    asm volatile(
        "mma.sync.aligned.m16n8k8.row.col.f32.tf32.tf32.f32 "
        "{%0,%1,%2,%3}, {%4,%5,%6,%7}, {%8,%9}, {%0,%1,%2,%3};\n"
        : "+f"(c[0]), "+f"(c[1]), "+f"(c[2]), "+f"(c[3])
        : "r"(a[0]), "r"(a[1]), "r"(a[2]), "r"(a[3]), "r"(b[0]), "r"(b[1]));
}

__device__ __forceinline__ void ldsm_x4(uint32_t& r0, uint32_t& r1, uint32_t& r2, uint32_t& r3,
                                        uint32_t saddr) {
    asm volatile("ldmatrix.sync.aligned.m8n8.x4.shared.b16 {%0,%1,%2,%3}, [%4];"
                 : "=r"(r0), "=r"(r1), "=r"(r2), "=r"(r3) : "r"(saddr));
}

__device__ __forceinline__ void cp_async16(uint32_t dst, const void* src) {
    asm volatile("cp.async.cg.shared.global [%0], [%1], 16;\n" :: "r"(dst), "l"(src));
}
__device__ __forceinline__ void cp_commit() { asm volatile("cp.async.commit_group;\n" ::: "memory"); }
template <int N>
__device__ __forceinline__ void cp_wait() { asm volatile("cp.async.wait_group %0;\n" :: "n"(N) : "memory"); }

// ---------------------------------------------------------------------------
// GEMM: Y[M,N] = X[M,K] @ W[N,K]^T + bias   (TN, both K-contiguous)
// 512 threads, 16 warps (4x4), warp tile 32x32, block tile 128x128, BK=32.
// 3-stage cp.async pipeline; smem holds raw fp32; tf32 cvt on fragments.
// (identical to the verified R3 kernel)
// ---------------------------------------------------------------------------
#define BM 128
#define BN 128
#define BK 32
#define LDAB 36          // u32 pitch: 144B, LDSM conflict-free
#define STAGES 3
#define SSZ (2 * 128 * LDAB)                 // u32 per stage (A then B)
#define GEMM_SMEM (STAGES * SSZ * 4)         // 110592 bytes

template <int MODE>
__global__ __launch_bounds__(512) void gemm_tn(
    const float* __restrict__ Xq, const float* __restrict__ Xk, const float* __restrict__ Xv,
    const float* __restrict__ Wp, const float* __restrict__ bp, float* __restrict__ Yp)
{
    extern __shared__ uint32_t smem_u[];
    const uint32_t smem_base = (uint32_t)__cvta_generic_to_shared(smem_u);

    const int z = blockIdx.z;
    const float* X;
    const float* Wz;
    const float* bz;
    if (MODE == 0) {
        X  = (z == 0) ? Xq : (z == 1) ? Xk : Xv;
        Wz = Wp + (size_t)z * D_MODEL * D_MODEL;
        bz = bp + z * D_MODEL;
    } else {
        X  = g_attn;
        Wz = Wp;
        bz = bp;
    }

    const int m0 = blockIdx.y * BM;
    const int n0 = blockIdx.x * BN;
    const int tid  = threadIdx.x;
    const int warp = tid >> 5, lane = tid & 31;
    const int wm = warp >> 2, wn = warp & 3;   // 4x4 warps, warp tile 32x32

    float acc[2][4][4];
#pragma unroll
    for (int mi = 0; mi < 2; mi++)
#pragma unroll
        for (int ni = 0; ni < 4; ni++)
#pragma unroll
            for (int r = 0; r < 4; r++) acc[mi][ni][r] = 0.f;

    const int lrow = tid >> 3;          // 0..63 (plus 64)
    const int lcol = (tid & 7) * 4;     // 0..28 step 4

    const uint32_t aRow = (lane & 15);
    const uint32_t aCol = (lane >> 4) * 4;
    const uint32_t bRow = ((lane >> 4) << 3) + (lane & 7);
    const uint32_t bCol = ((lane >> 3) & 1) * 4;

    auto issue_stage = [&](int s, int kt) {
        const uint32_t sa = smem_base + (uint32_t)s * SSZ * 4;
        const uint32_t sb = sa + 128 * LDAB * 4;
#pragma unroll
        for (int i = 0; i < 2; i++) {
            const int r = lrow + i * 64;
            cp_async16(sa + (r * LDAB + lcol) * 4, &X [(size_t)(m0 + r) * D_MODEL + kt + lcol]);
            cp_async16(sb + (r * LDAB + lcol) * 4, &Wz[(size_t)(n0 + r) * D_MODEL + kt + lcol]);
        }
    };

    int kt_load = 0;
#pragma unroll
    for (int s = 0; s < STAGES - 1; s++) {
        issue_stage(s, kt_load);
        cp_commit();
        kt_load += BK;
    }

    int sc = 0;
    for (int kt = 0; kt < D_MODEL; kt += BK) {
        cp_wait<STAGES - 2>();
        __syncthreads();

        if (kt_load < D_MODEL) {
            int sl = sc + STAGES - 1; if (sl >= STAGES) sl -= STAGES;
            issue_stage(sl, kt_load);
            kt_load += BK;
        }
        cp_commit();

        const uint32_t sA = smem_base + (uint32_t)sc * SSZ * 4;
        const uint32_t sB = sA + 128 * LDAB * 4;

#pragma unroll
        for (int k8 = 0; k8 < 4; k8++) {
            uint32_t afr[2][4];
            uint32_t bfr[4][2];
#pragma unroll
            for (int mi = 0; mi < 2; mi++) {
                uint32_t addr = sA + (((wm * 32 + mi * 16 + aRow) * LDAB) + k8 * 8 + aCol) * 4;
                ldsm_x4(afr[mi][0], afr[mi][1], afr[mi][2], afr[mi][3], addr);
            }
#pragma unroll
            for (int p = 0; p < 2; p++) {
                uint32_t addr = sB + (((wn * 32 + p * 16 + bRow) * LDAB) + k8 * 8 + bCol) * 4;
                ldsm_x4(bfr[2 * p][0], bfr[2 * p][1], bfr[2 * p + 1][0], bfr[2 * p + 1][1], addr);
            }
#pragma unroll
            for (int mi = 0; mi < 2; mi++)
#pragma unroll
                for (int r = 0; r < 4; r++) afr[mi][r] = u2tf32(afr[mi][r]);
#pragma unroll
            for (int ni = 0; ni < 4; ni++) {
                bfr[ni][0] = u2tf32(bfr[ni][0]);
                bfr[ni][1] = u2tf32(bfr[ni][1]);
            }
#pragma unroll
            for (int mi = 0; mi < 2; mi++)
#pragma unroll
                for (int ni = 0; ni < 4; ni++)
                    mma_tf32(acc[mi][ni], afr[mi], bfr[ni]);
        }
        sc++; if (sc == STAGES) sc = 0;
        __syncthreads();
    }

#pragma unroll
    for (int mi = 0; mi < 2; mi++) {
#pragma unroll
        for (int ni = 0; ni < 4; ni++) {
            int r0 = m0 + wm * 32 + mi * 16 + (lane >> 2);
            int c0 = n0 + wn * 32 + ni * 8 + (lane & 3) * 2;
#pragma unroll
            for (int e = 0; e < 4; e++) {
                int m = r0 + ((e >= 2) ? 8 : 0);
                int n = c0 + (e & 1);
                float v = acc[mi][ni][e] + bz[n];
                if (MODE == 0) {
                    int b = m >> 12;
                    int l = m & 4095;
                    int w = l >> 7, rr = l & 127;
                    int h = n >> 6, d = n & 63;
                    size_t idx = ((((size_t)((b * NW + w) * NHEAD + h)) * WIN + rr) * HDIM) + d;
                    g_qkv[(size_t)z * QKV_STRIDE + idx] = v;
                } else {
                    Yp[(size_t)m * D_MODEL + n] = v;
                }
            }
        }
    }
}

// ---------------------------------------------------------------------------
// Windowed attention with mma.sync tf32. One CTA (256 thr) per (b,w,h).
// smem (u32 units): sq[128][68] tf32 (Q*scale), sk[128][68] tf32,
//                   sv[128][72] fp32 V, sp[128][132] scores/P, sinv[128].
// ---------------------------------------------------------------------------
#define AQP 68     // pitch for sq/sk (u32), 4 mod 32 -> ldmatrix conflict-free
#define AVP 72     // pitch for sv, 8 mod 32 -> scalar B loads conflict-free
#define APP 132    // pitch for sp, 4 mod 32
#define SQ_OFF 0
#define SK_OFF (128 * AQP)                 // 8704
#define SV_OFF (SK_OFF + 128 * AQP)        // 17408
#define SP_OFF (SV_OFF + 128 * AVP)        // 26624
#define SI_OFF (SP_OFF + 128 * APP)        // 43520
#define ATTN_SMEM ((SI_OFF + 128) * 4)     // 174592 bytes

__global__ __launch_bounds__(256) void attn_kernel() {
    extern __shared__ uint32_t su[];
    float* sf = reinterpret_cast<float*>(su);
    const uint32_t sbase = (uint32_t)__cvta_generic_to_shared(su);

    const int bid = blockIdx.x;
    const int h = bid & 15;
    const int w = (bid >> 4) & 31;
    const int b = bid >> 9;
    const size_t tile = ((size_t)((b * NW + w) * NHEAD + h)) * (WIN * HDIM);

    const float* gq = g_qkv + tile;
    const float* gk = g_qkv + QKV_STRIDE + tile;
    const float* gv = g_qkv + 2 * QKV_STRIDE + tile;

    const int tid = threadIdx.x;
    const int warp = tid >> 5, lane = tid & 31;

    // ---- staging: Q (scaled, tf32), K (tf32), V (fp32) ----
    const float scale = 0.125f;   // 1/sqrt(64)
#pragma unroll
    for (int i = 0; i < 8; i++) {
        int idx = tid + i * 256;          // 2048 float4 slots
        int r = idx >> 4;
        int c = (idx & 15) * 4;
        float4 qv = *(const float4*)&gq[r * HDIM + c];
        *(uint4*)&su[SQ_OFF + r * AQP + c] =
            make_uint4(f2tf32(qv.x * scale), f2tf32(qv.y * scale),
                       f2tf32(qv.z * scale), f2tf32(qv.w * scale));
        float4 kv = *(const float4*)&gk[r * HDIM + c];
        *(uint4*)&su[SK_OFF + r * AQP + c] =
            make_uint4(f2tf32(kv.x), f2tf32(kv.y), f2tf32(kv.z), f2tf32(kv.w));
        float4 vv = *(const float4*)&gv[r * HDIM + c];
        *(float4*)&sf[SV_OFF + r * AVP + c] = vv;
    }
    __syncthreads();

    const uint32_t aRow = (lane & 15);
    const uint32_t aCol = (lane >> 4) * 4;
    const uint32_t bRow = ((lane >> 4) << 3) + (lane & 7);
    const uint32_t bCol = ((lane >> 3) & 1) * 4;

    // ---- Phase B: S = (Q*scale) @ K^T.  4x2 warps, warp tile 32x64 ----
    {
        const int wm = warp >> 1, wn = warp & 1;
        float acc[2][8][4];
#pragma unroll
        for (int mi = 0; mi < 2; mi++)
#pragma unroll
            for (int ni = 0; ni < 8; ni++)
#pragma unroll
                for (int e = 0; e < 4; e++) acc[mi][ni][e] = 0.f;

#pragma unroll
        for (int k8 = 0; k8 < 8; k8++) {
            uint32_t afr[2][4], bfr[8][2];
#pragma unroll
            for (int mi = 0; mi < 2; mi++) {
                uint32_t addr = sbase + (SQ_OFF + (wm * 32 + mi * 16 + aRow) * AQP + k8 * 8 + aCol) * 4;
                ldsm_x4(afr[mi][0], afr[mi][1], afr[mi][2], afr[mi][3], addr);
            }
#pragma unroll
            for (int p = 0; p < 4; p++) {
                uint32_t addr = sbase + (SK_OFF + (wn * 64 + p * 16 + bRow) * AQP + k8 * 8 + bCol) * 4;
                ldsm_x4(bfr[2 * p][0], bfr[2 * p][1], bfr[2 * p + 1][0], bfr[2 * p + 1][1], addr);
            }
#pragma unroll
            for (int mi = 0; mi < 2; mi++)
#pragma unroll
                for (int ni = 0; ni < 8; ni++)
                    mma_tf32(acc[mi][ni], afr[mi], bfr[ni]);
        }

        // write raw scores (fp32) to sp
#pragma unroll
        for (int mi = 0; mi < 2; mi++) {
            const int r0 = wm * 32 + mi * 16 + (lane >> 2);
#pragma unroll
            for (int ni = 0; ni < 8; ni++) {
                const int c0 = wn * 64 + ni * 8 + (lane & 3) * 2;
                *(float2*)&sf[SP_OFF + r0 * APP + c0]       = make_float2(acc[mi][ni][0], acc[mi][ni][1]);
                *(float2*)&sf[SP_OFF + (r0 + 8) * APP + c0] = make_float2(acc[mi][ni][2], acc[mi][ni][3]);
            }
        }
    }
    __syncthreads();

    // ---- softmax: 2 threads per row ----
    {
        const int r = tid >> 1;
        const int half = (tid & 1) * 64;
        float* row = &sf[SP_OFF + r * APP + half];
        float mx = -1e30f;
#pragma unroll 8
        for (int j = 0; j < 64; j++) mx = fmaxf(mx, row[j]);
        mx = fmaxf(mx, __shfl_xor_sync(0xffffffff, mx, 1));
        float sum = 0.f;
#pragma unroll 8
        for (int j = 0; j < 64; j++) {
            float e = __expf(row[j] - mx);
            sum += e;
            su[SP_OFF + r * APP + half + j] = f2tf32(e);   // store P as tf32 bits
        }
        sum += __shfl_xor_sync(0xffffffff, sum, 1);
        if ((tid & 1) == 0) sf[SI_OFF + r] = 1.f / sum;
    }
    __syncthreads();

    // ---- Phase D: O = P @ V.  8 warps, warp tile 16x64 ----
    {
        float oacc[8][4];
#pragma unroll
        for (int n = 0; n < 8; n++)
#pragma unroll
            for (int e = 0; e < 4; e++) oacc[n][e] = 0.f;

        const int mrow = warp * 16;
        const int bj = lane & 3;        // k offset within step
        const int bd = lane >> 2;       // n offset

#pragma unroll
        for (int k8 = 0; k8 < 16; k8++) {
            uint32_t afr[4];
            uint32_t addr = sbase + (SP_OFF + (mrow + aRow) * APP + k8 * 8 + aCol) * 4;
            ldsm_x4(afr[0], afr[1], afr[2], afr[3], addr);
#pragma unroll
            for (int n = 0; n < 8; n++) {
                uint32_t bfr[2];
                bfr[0] = f2tf32(sf[SV_OFF + (k8 * 8 + bj) * AVP + n * 8 + bd]);
                bfr[1] = f2tf32(sf[SV_OFF + (k8 * 8 + 4 + bj) * AVP + n * 8 + bd]);
                mma_tf32(oacc[n], afr, bfr);
            }
        }

        // epilogue: normalize rows, store to g_attn
        const int r0 = mrow + (lane >> 2);
        const float inv0 = sf[SI_OFF + r0];
        const float inv1 = sf[SI_OFF + r0 + 8];
        const size_t gb0 = ((size_t)b * SEQ + (size_t)w * WIN + r0) * D_MODEL + h * HDIM;
        const size_t gb1 = gb0 + 8ull * D_MODEL;
#pragma unroll
        for (int n = 0; n < 8; n++) {
            const int c0 = n * 8 + (lane & 3) * 2;
            *(float2*)&g_attn[gb0 + c0] = make_float2(oacc[n][0] * inv0, oacc[n][1] * inv0);
            *(float2*)&g_attn[gb1 + c0] = make_float2(oacc[n][2] * inv1, oacc[n][3] * inv1);
        }
    }
}

// ---------------------------------------------------------------------------
extern "C" void kernel_launch(void* const* d_in, const int* in_sizes, int n_in,
                              void* d_out, int out_size) {
    const float* q   = (const float*)d_in[0];
    const float* k   = (const float*)d_in[1];
    const float* v   = (const float*)d_in[2];
    const float* ipw = (const float*)d_in[3];
    const float* ipb = (const float*)d_in[4];
    const float* ow  = (const float*)d_in[5];
    const float* ob  = (const float*)d_in[6];
    float* out = (float*)d_out;

    cudaFuncSetAttribute(gemm_tn<0>, cudaFuncAttributeMaxDynamicSharedMemorySize, GEMM_SMEM);
    cudaFuncSetAttribute(gemm_tn<1>, cudaFuncAttributeMaxDynamicSharedMemorySize, GEMM_SMEM);
    cudaFuncSetAttribute(attn_kernel, cudaFuncAttributeMaxDynamicSharedMemorySize, ATTN_SMEM);

    // 1) QKV projection
    dim3 g0(D_MODEL / BN, M_TOTAL / BM, 3);
    gemm_tn<0><<<g0, 512, GEMM_SMEM>>>(q, k, v, ipw, ipb, nullptr);

    // 2) Windowed attention: 2048 blocks
    attn_kernel<<<BATCH * NW * NHEAD, 256, ATTN_SMEM>>>();

    // 3) Output projection
    dim3 g1(D_MODEL / BN, M_TOTAL / BM, 1);
    gemm_tn<1><<<g1, 512, GEMM_SMEM>>>(nullptr, nullptr, nullptr, ow, ob, out);
}

// round 8
// speedup vs baseline: 1.7202x; 1.0384x over previous
#include <cuda_runtime.h>
#include <cstdint>
#include <cstdio>

#define D_MODEL 1024
#define NHEAD   16
#define HDIM    64
#define WIN     128
#define BATCH   4
#define SEQ     4096
#define NW      (SEQ / WIN)            // 32
#define M_TOTAL (BATCH * SEQ)          // 16384
#define QKV_STRIDE ((size_t)M_TOTAL * D_MODEL)  // 16777216

// Scratch (allocation-free rule: device globals)
__device__ float    g_qkv[3ull * M_TOTAL * D_MODEL];     // fp32 attention tiles
__device__ uint32_t g_x32[3ull * M_TOTAL * D_MODEL];     // tf32 q,k,v
__device__ uint32_t g_w32[3ull * D_MODEL * D_MODEL];     // tf32 in_proj_w
__device__ uint32_t g_ow32[(size_t)D_MODEL * D_MODEL];   // tf32 out_w
__device__ uint32_t g_attn32[(size_t)M_TOTAL * D_MODEL]; // tf32 attention output

// ---------------------------------------------------------------------------
// TF32 / MMA / async helpers (generic-target ISA only; tcgen05 is rejected by
// the harness ptxas which targets plain sm_103)
// ---------------------------------------------------------------------------
__device__ __forceinline__ uint32_t f2tf32(float f) {
    uint32_t u;
    asm("cvt.rna.tf32.f32 %0, %1;" : "=r"(u) : "f"(f));
    return u;
}

__device__ __forceinline__ void mma_tf32(float c[4], const uint32_t a[4], const uint32_t b[2]) {
    asm volatile(
        "mma.sync.aligned.m16n8k8.row.col.f32.tf32.tf32.f32 "
        "{%0,%1,%2,%3}, {%4,%5,%6,%7}, {%8,%9}, {%0,%1,%2,%3};\n"
        : "+f"(c[0]), "+f"(c[1]), "+f"(c[2]), "+f"(c[3])
        : "r"(a[0]), "r"(a[1]), "r"(a[2]), "r"(a[3]), "r"(b[0]), "r"(b[1]));
}

__device__ __forceinline__ void ldsm_x4(uint32_t& r0, uint32_t& r1, uint32_t& r2, uint32_t& r3,
                                        uint32_t saddr) {
    asm volatile("ldmatrix.sync.aligned.m8n8.x4.shared.b16 {%0,%1,%2,%3}, [%4];"
                 : "=r"(r0), "=r"(r1), "=r"(r2), "=r"(r3) : "r"(saddr));
}

__device__ __forceinline__ void cp_async16(uint32_t dst, const void* src) {
    asm volatile("cp.async.cg.shared.global [%0], [%1], 16;\n" :: "r"(dst), "l"(src));
}
__device__ __forceinline__ void cp_commit() { asm volatile("cp.async.commit_group;\n" ::: "memory"); }
template <int N>
__device__ __forceinline__ void cp_wait() { asm volatile("cp.async.wait_group %0;\n" :: "n"(N) : "memory"); }

// ---------------------------------------------------------------------------
// Prepass: fp32 -> tf32-bit conversion (pure bandwidth)
// ---------------------------------------------------------------------------
__global__ __launch_bounds__(256) void cvt_pass(const float* __restrict__ src,
                                                uint32_t* __restrict__ dst, int n4) {
    int i = blockIdx.x * 256 + threadIdx.x;
    int stride = gridDim.x * 256;
    for (; i < n4; i += stride) {
        float4 v = *(const float4*)&src[4 * i];
        *(uint4*)&dst[4 * i] = make_uint4(f2tf32(v.x), f2tf32(v.y), f2tf32(v.z), f2tf32(v.w));
    }
}

// ---------------------------------------------------------------------------
// GEMM: Y[M,N] = X[M,K] @ W[N,K]^T + bias   (TN, both K-contiguous)
// Inputs are pre-converted tf32 bits. 512 threads, 16 warps (4x4),
// warp tile 32x32, block tile 128x128, BK=32, 3-stage cp.async pipeline.
// Inner loop: LDSM + MMA only (no cvt).
// ---------------------------------------------------------------------------
#define BM 128
#define BN 128
#define BK 32
#define LDAB 36          // u32 pitch: 144B, LDSM conflict-free
#define STAGES 3
#define SSZ (2 * 128 * LDAB)                 // u32 per stage (A then B)
#define GEMM_SMEM (STAGES * SSZ * 4)         // 110592 bytes

template <int MODE>
__global__ __launch_bounds__(512) void gemm_tn(
    const float* __restrict__ bp, float* __restrict__ Yp)
{
    extern __shared__ uint32_t smem_u[];
    const uint32_t smem_base = (uint32_t)__cvta_generic_to_shared(smem_u);

    const int z = blockIdx.z;
    const uint32_t* X;
    const uint32_t* Wz;
    const float* bz;
    if (MODE == 0) {
        X  = g_x32 + (size_t)z * QKV_STRIDE;
        Wz = g_w32 + (size_t)z * D_MODEL * D_MODEL;
        bz = bp + z * D_MODEL;
    } else {
        X  = g_attn32;
        Wz = g_ow32;
        bz = bp;
    }

    const int m0 = blockIdx.y * BM;
    const int n0 = blockIdx.x * BN;
    const int tid  = threadIdx.x;
    const int warp = tid >> 5, lane = tid & 31;
    const int wm = warp >> 2, wn = warp & 3;   // 4x4 warps, warp tile 32x32

    float acc[2][4][4];
#pragma unroll
    for (int mi = 0; mi < 2; mi++)
#pragma unroll
        for (int ni = 0; ni < 4; ni++)
#pragma unroll
            for (int r = 0; r < 4; r++) acc[mi][ni][r] = 0.f;

    const int lrow = tid >> 3;          // 0..63 (plus 64)
    const int lcol = (tid & 7) * 4;     // 0..28 step 4

    const uint32_t aRow = (lane & 15);
    const uint32_t aCol = (lane >> 4) * 4;
    const uint32_t bRow = ((lane >> 4) << 3) + (lane & 7);
    const uint32_t bCol = ((lane >> 3) & 1) * 4;

    auto issue_stage = [&](int s, int kt) {
        const uint32_t sa = smem_base + (uint32_t)s * SSZ * 4;
        const uint32_t sb = sa + 128 * LDAB * 4;
#pragma unroll
        for (int i = 0; i < 2; i++) {
            const int r = lrow + i * 64;
            cp_async16(sa + (r * LDAB + lcol) * 4, &X [(size_t)(m0 + r) * D_MODEL + kt + lcol]);
            cp_async16(sb + (r * LDAB + lcol) * 4, &Wz[(size_t)(n0 + r) * D_MODEL + kt + lcol]);
        }
    };

    int kt_load = 0;
#pragma unroll
    for (int s = 0; s < STAGES - 1; s++) {
        issue_stage(s, kt_load);
        cp_commit();
        kt_load += BK;
    }

    int sc = 0;
    for (int kt = 0; kt < D_MODEL; kt += BK) {
        cp_wait<STAGES - 2>();
        __syncthreads();

        if (kt_load < D_MODEL) {
            int sl = sc + STAGES - 1; if (sl >= STAGES) sl -= STAGES;
            issue_stage(sl, kt_load);
            kt_load += BK;
        }
        cp_commit();

        const uint32_t sA = smem_base + (uint32_t)sc * SSZ * 4;
        const uint32_t sB = sA + 128 * LDAB * 4;

#pragma unroll
        for (int k8 = 0; k8 < 4; k8++) {
            uint32_t afr[2][4];
            uint32_t bfr[4][2];
#pragma unroll
            for (int mi = 0; mi < 2; mi++) {
                uint32_t addr = sA + (((wm * 32 + mi * 16 + aRow) * LDAB) + k8 * 8 + aCol) * 4;
                ldsm_x4(afr[mi][0], afr[mi][1], afr[mi][2], afr[mi][3], addr);
            }
#pragma unroll
            for (int p = 0; p < 2; p++) {
                uint32_t addr = sB + (((wn * 32 + p * 16 + bRow) * LDAB) + k8 * 8 + bCol) * 4;
                ldsm_x4(bfr[2 * p][0], bfr[2 * p][1], bfr[2 * p + 1][0], bfr[2 * p + 1][1], addr);
            }
#pragma unroll
            for (int mi = 0; mi < 2; mi++)
#pragma unroll
                for (int ni = 0; ni < 4; ni++)
                    mma_tf32(acc[mi][ni], afr[mi], bfr[ni]);
        }
        sc++; if (sc == STAGES) sc = 0;
        __syncthreads();
    }

#pragma unroll
    for (int mi = 0; mi < 2; mi++) {
#pragma unroll
        for (int ni = 0; ni < 4; ni++) {
            int r0 = m0 + wm * 32 + mi * 16 + (lane >> 2);
            int c0 = n0 + wn * 32 + ni * 8 + (lane & 3) * 2;
#pragma unroll
            for (int e = 0; e < 4; e++) {
                int m = r0 + ((e >= 2) ? 8 : 0);
                int n = c0 + (e & 1);
                float v = acc[mi][ni][e] + bz[n];
                if (MODE == 0) {
                    int b = m >> 12;
                    int l = m & 4095;
                    int w = l >> 7, rr = l & 127;
                    int h = n >> 6, d = n & 63;
                    size_t idx = ((((size_t)((b * NW + w) * NHEAD + h)) * WIN + rr) * HDIM) + d;
                    g_qkv[(size_t)z * QKV_STRIDE + idx] = v;
                } else {
                    Yp[(size_t)m * D_MODEL + n] = v;
                }
            }
        }
    }
}

// ---------------------------------------------------------------------------
// Windowed attention with mma.sync tf32. One CTA (256 thr) per (b,w,h).
// smem (u32 units): sq[128][68] tf32 (Q*scale), sk[128][68] tf32,
//                   sv[128][72] fp32 V, sp[128][132] scores/P, sinv[128].
// Output written as tf32 bits to g_attn32 (consumed by out-proj GEMM).
// ---------------------------------------------------------------------------
#define AQP 68
#define AVP 72
#define APP 132
#define SQ_OFF 0
#define SK_OFF (128 * AQP)
#define SV_OFF (SK_OFF + 128 * AQP)
#define SP_OFF (SV_OFF + 128 * AVP)
#define SI_OFF (SP_OFF + 128 * APP)
#define ATTN_SMEM ((SI_OFF + 128) * 4)     // 174592 bytes

__global__ __launch_bounds__(256) void attn_kernel() {
    extern __shared__ uint32_t su[];
    float* sf = reinterpret_cast<float*>(su);
    const uint32_t sbase = (uint32_t)__cvta_generic_to_shared(su);

    const int bid = blockIdx.x;
    const int h = bid & 15;
    const int w = (bid >> 4) & 31;
    const int b = bid >> 9;
    const size_t tile = ((size_t)((b * NW + w) * NHEAD + h)) * (WIN * HDIM);

    const float* gq = g_qkv + tile;
    const float* gk = g_qkv + QKV_STRIDE + tile;
    const float* gv = g_qkv + 2 * QKV_STRIDE + tile;

    const int tid = threadIdx.x;
    const int warp = tid >> 5, lane = tid & 31;

    const float scale = 0.125f;   // 1/sqrt(64)
#pragma unroll
    for (int i = 0; i < 8; i++) {
        int idx = tid + i * 256;
        int r = idx >> 4;
        int c = (idx & 15) * 4;
        float4 qv = *(const float4*)&gq[r * HDIM + c];
        *(uint4*)&su[SQ_OFF + r * AQP + c] =
            make_uint4(f2tf32(qv.x * scale), f2tf32(qv.y * scale),
                       f2tf32(qv.z * scale), f2tf32(qv.w * scale));
        float4 kv = *(const float4*)&gk[r * HDIM + c];
        *(uint4*)&su[SK_OFF + r * AQP + c] =
            make_uint4(f2tf32(kv.x), f2tf32(kv.y), f2tf32(kv.z), f2tf32(kv.w));
        float4 vv = *(const float4*)&gv[r * HDIM + c];
        *(float4*)&sf[SV_OFF + r * AVP + c] = vv;
    }
    __syncthreads();

    const uint32_t aRow = (lane & 15);
    const uint32_t aCol = (lane >> 4) * 4;
    const uint32_t bRow = ((lane >> 4) << 3) + (lane & 7);
    const uint32_t bCol = ((lane >> 3) & 1) * 4;

    // ---- Phase B: S = (Q*scale) @ K^T.  4x2 warps, warp tile 32x64 ----
    {
        const int wm = warp >> 1, wn = warp & 1;
        float acc[2][8][4];
#pragma unroll
        for (int mi = 0; mi < 2; mi++)
#pragma unroll
            for (int ni = 0; ni < 8; ni++)
#pragma unroll
                for (int e = 0; e < 4; e++) acc[mi][ni][e] = 0.f;

#pragma unroll
        for (int k8 = 0; k8 < 8; k8++) {
            uint32_t afr[2][4], bfr[8][2];
#pragma unroll
            for (int mi = 0; mi < 2; mi++) {
                uint32_t addr = sbase + (SQ_OFF + (wm * 32 + mi * 16 + aRow) * AQP + k8 * 8 + aCol) * 4;
                ldsm_x4(afr[mi][0], afr[mi][1], afr[mi][2], afr[mi][3], addr);
            }
#pragma unroll
            for (int p = 0; p < 4; p++) {
                uint32_t addr = sbase + (SK_OFF + (wn * 64 + p * 16 + bRow) * AQP + k8 * 8 + bCol) * 4;
                ldsm_x4(bfr[2 * p][0], bfr[2 * p][1], bfr[2 * p + 1][0], bfr[2 * p + 1][1], addr);
            }
#pragma unroll
            for (int mi = 0; mi < 2; mi++)
#pragma unroll
                for (int ni = 0; ni < 8; ni++)
                    mma_tf32(acc[mi][ni], afr[mi], bfr[ni]);
        }

#pragma unroll
        for (int mi = 0; mi < 2; mi++) {
            const int r0 = wm * 32 + mi * 16 + (lane >> 2);
#pragma unroll
            for (int ni = 0; ni < 8; ni++) {
                const int c0 = wn * 64 + ni * 8 + (lane & 3) * 2;
                *(float2*)&sf[SP_OFF + r0 * APP + c0]       = make_float2(acc[mi][ni][0], acc[mi][ni][1]);
                *(float2*)&sf[SP_OFF + (r0 + 8) * APP + c0] = make_float2(acc[mi][ni][2], acc[mi][ni][3]);
            }
        }
    }
    __syncthreads();

    // ---- softmax: 2 threads per row ----
    {
        const int r = tid >> 1;
        const int half = (tid & 1) * 64;
        float* row = &sf[SP_OFF + r * APP + half];
        float mx = -1e30f;
#pragma unroll 8
        for (int j = 0; j < 64; j++) mx = fmaxf(mx, row[j]);
        mx = fmaxf(mx, __shfl_xor_sync(0xffffffff, mx, 1));
        float sum = 0.f;
#pragma unroll 8
        for (int j = 0; j < 64; j++) {
            float e = __expf(row[j] - mx);
            sum += e;
            su[SP_OFF + r * APP + half + j] = f2tf32(e);   // store P as tf32 bits
        }
        sum += __shfl_xor_sync(0xffffffff, sum, 1);
        if ((tid & 1) == 0) sf[SI_OFF + r] = 1.f / sum;
    }
    __syncthreads();

    // ---- Phase D: O = P @ V.  8 warps, warp tile 16x64 ----
    {
        float oacc[8][4];
#pragma unroll
        for (int n = 0; n < 8; n++)
#pragma unroll
            for (int e = 0; e < 4; e++) oacc[n][e] = 0.f;

        const int mrow = warp * 16;
        const int bj = lane & 3;
        const int bd = lane >> 2;

#pragma unroll
        for (int k8 = 0; k8 < 16; k8++) {
            uint32_t afr[4];
            uint32_t addr = sbase + (SP_OFF + (mrow + aRow) * APP + k8 * 8 + aCol) * 4;
            ldsm_x4(afr[0], afr[1], afr[2], afr[3], addr);
#pragma unroll
            for (int n = 0; n < 8; n++) {
                uint32_t bfr[2];
                bfr[0] = f2tf32(sf[SV_OFF + (k8 * 8 + bj) * AVP + n * 8 + bd]);
                bfr[1] = f2tf32(sf[SV_OFF + (k8 * 8 + 4 + bj) * AVP + n * 8 + bd]);
                mma_tf32(oacc[n], afr, bfr);
            }
        }

        // epilogue: normalize rows, store tf32 bits to g_attn32
        const int r0 = mrow + (lane >> 2);
        const float inv0 = sf[SI_OFF + r0];
        const float inv1 = sf[SI_OFF + r0 + 8];
        const size_t gb0 = ((size_t)b * SEQ + (size_t)w * WIN + r0) * D_MODEL + h * HDIM;
        const size_t gb1 = gb0 + 8ull * D_MODEL;
#pragma unroll
        for (int n = 0; n < 8; n++) {
            const int c0 = n * 8 + (lane & 3) * 2;
            *(uint2*)&g_attn32[gb0 + c0] =
                make_uint2(f2tf32(oacc[n][0] * inv0), f2tf32(oacc[n][1] * inv0));
            *(uint2*)&g_attn32[gb1 + c0] =
                make_uint2(f2tf32(oacc[n][2] * inv1), f2tf32(oacc[n][3] * inv1));
        }
    }
}

// ---------------------------------------------------------------------------
extern "C" void kernel_launch(void* const* d_in, const int* in_sizes, int n_in,
                              void* d_out, int out_size) {
    const float* q   = (const float*)d_in[0];
    const float* k   = (const float*)d_in[1];
    const float* v   = (const float*)d_in[2];
    const float* ipw = (const float*)d_in[3];
    const float* ipb = (const float*)d_in[4];
    const float* ow  = (const float*)d_in[5];
    const float* ob  = (const float*)d_in[6];
    float* out = (float*)d_out;

    cudaFuncSetAttribute(gemm_tn<0>, cudaFuncAttributeMaxDynamicSharedMemorySize, GEMM_SMEM);
    cudaFuncSetAttribute(gemm_tn<1>, cudaFuncAttributeMaxDynamicSharedMemorySize, GEMM_SMEM);
    cudaFuncSetAttribute(attn_kernel, cudaFuncAttributeMaxDynamicSharedMemorySize, ATTN_SMEM);

    uint32_t* x32;  cudaGetSymbolAddress((void**)&x32,  g_x32);
    uint32_t* w32;  cudaGetSymbolAddress((void**)&w32,  g_w32);
    uint32_t* ow32; cudaGetSymbolAddress((void**)&ow32, g_ow32);

    // 0) tf32 prepass (pure bandwidth)
    cvt_pass<<<2048, 256>>>(q, x32,                     M_TOTAL * D_MODEL / 4);
    cvt_pass<<<2048, 256>>>(k, x32 + QKV_STRIDE,        M_TOTAL * D_MODEL / 4);
    cvt_pass<<<2048, 256>>>(v, x32 + 2 * QKV_STRIDE,    M_TOTAL * D_MODEL / 4);
    cvt_pass<<<512,  256>>>(ipw, w32,                   3 * D_MODEL * D_MODEL / 4);
    cvt_pass<<<256,  256>>>(ow,  ow32,                  D_MODEL * D_MODEL / 4);

    // 1) QKV projection
    dim3 g0(D_MODEL / BN, M_TOTAL / BM, 3);
    gemm_tn<0><<<g0, 512, GEMM_SMEM>>>(ipb, nullptr);

    // 2) Windowed attention: 2048 blocks
    attn_kernel<<<BATCH * NW * NHEAD, 256, ATTN_SMEM>>>();

    // 3) Output projection
    dim3 g1(D_MODEL / BN, M_TOTAL / BM, 1);
    gemm_tn<1><<<g1, 512, GEMM_SMEM>>>(ob, out);
}

// round 9
// speedup vs baseline: 2.9328x; 1.7050x over previous
#include <cuda_runtime.h>
#include <cuda_fp16.h>
#include <cstdint>
#include <cstdio>

#define D_MODEL 1024
#define NHEAD   16
#define HDIM    64
#define WIN     128
#define BATCH   4
#define SEQ     4096
#define NW      (SEQ / WIN)            // 32
#define M_TOTAL (BATCH * SEQ)          // 16384
#define QKV_STRIDE ((size_t)M_TOTAL * D_MODEL)  // 16777216

// Scratch (allocation-free rule: device globals)
__device__ __half g_x16[3ull * M_TOTAL * D_MODEL];    // fp16 q,k,v inputs
__device__ __half g_w16[3ull * D_MODEL * D_MODEL];    // fp16 in_proj_w
__device__ __half g_ow16[(size_t)D_MODEL * D_MODEL];  // fp16 out_w
__device__ __half g_qkv16[3ull * M_TOTAL * D_MODEL];  // fp16 attention tiles (Q pre-scaled)
__device__ __half g_attn16[(size_t)M_TOTAL * D_MODEL];// fp16 attention output

// ---------------------------------------------------------------------------
// helpers (generic-target ISA only; tcgen05 rejected by harness ptxas sm_103)
// ---------------------------------------------------------------------------
__device__ __forceinline__ void mma_f16(float c[4], const uint32_t a[4], const uint32_t b[2]) {
    asm volatile(
        "mma.sync.aligned.m16n8k16.row.col.f32.f16.f16.f32 "
        "{%0,%1,%2,%3}, {%4,%5,%6,%7}, {%8,%9}, {%0,%1,%2,%3};\n"
        : "+f"(c[0]), "+f"(c[1]), "+f"(c[2]), "+f"(c[3])
        : "r"(a[0]), "r"(a[1]), "r"(a[2]), "r"(a[3]), "r"(b[0]), "r"(b[1]));
}

__device__ __forceinline__ void ldsm_x4(uint32_t& r0, uint32_t& r1, uint32_t& r2, uint32_t& r3,
                                        uint32_t saddr) {
    asm volatile("ldmatrix.sync.aligned.m8n8.x4.shared.b16 {%0,%1,%2,%3}, [%4];"
                 : "=r"(r0), "=r"(r1), "=r"(r2), "=r"(r3) : "r"(saddr));
}
__device__ __forceinline__ void ldsm_x4_t(uint32_t& r0, uint32_t& r1, uint32_t& r2, uint32_t& r3,
                                          uint32_t saddr) {
    asm volatile("ldmatrix.sync.aligned.m8n8.x4.trans.shared.b16 {%0,%1,%2,%3}, [%4];"
                 : "=r"(r0), "=r"(r1), "=r"(r2), "=r"(r3) : "r"(saddr));
}

__device__ __forceinline__ void cp_async16(uint32_t dst, const void* src) {
    asm volatile("cp.async.cg.shared.global [%0], [%1], 16;\n" :: "r"(dst), "l"(src));
}
__device__ __forceinline__ void cp_commit() { asm volatile("cp.async.commit_group;\n" ::: "memory"); }
template <int N>
__device__ __forceinline__ void cp_wait() { asm volatile("cp.async.wait_group %0;\n" :: "n"(N) : "memory"); }

// ---------------------------------------------------------------------------
// Prepass: fp32 -> fp16 (pure bandwidth)
// ---------------------------------------------------------------------------
__global__ __launch_bounds__(256) void cvt_half(const float* __restrict__ src,
                                                __half* __restrict__ dst, int n4) {
    int i = blockIdx.x * 256 + threadIdx.x;
    int stride = gridDim.x * 256;
    for (; i < n4; i += stride) {
        float4 v = *(const float4*)&src[4 * i];
        __half2 lo = __floats2half2_rn(v.x, v.y);
        __half2 hi = __floats2half2_rn(v.z, v.w);
        *(uint2*)&dst[4 * i] = make_uint2(*(uint32_t*)&lo, *(uint32_t*)&hi);
    }
}

// ---------------------------------------------------------------------------
// fp16 GEMM: Y[M,N] = X[M,K] @ W[N,K]^T + bias   (TN, both K-contiguous)
// 512 threads, 16 warps (4x4), warp tile 32x32, block tile 128x128, BK=32.
// 3-stage cp.async pipeline. Inner loop: LDSM + HMMA.16816 only.
// ---------------------------------------------------------------------------
#define BM 128
#define BN 128
#define BK 32
#define PH 40                                 // halves pitch: 80B, conflict-free
#define STG_MAT (128 * PH * 2)                // 10240 B per matrix
#define STG_BYTES (2 * STG_MAT)               // 20480 B per stage
#define STAGES 3
#define GEMM_SMEM (STAGES * STG_BYTES)        // 61440 B

template <int MODE>
__global__ __launch_bounds__(512) void gemm_f16(
    const float* __restrict__ bp, float* __restrict__ Yp)
{
    extern __shared__ uint8_t smem[];
    const uint32_t smem_base = (uint32_t)__cvta_generic_to_shared(smem);

    const int z = blockIdx.z;
    const __half* X;
    const __half* Wz;
    const float* bz;
    if (MODE == 0) {
        X  = g_x16 + (size_t)z * QKV_STRIDE;
        Wz = g_w16 + (size_t)z * D_MODEL * D_MODEL;
        bz = bp + z * D_MODEL;
    } else {
        X  = g_attn16;
        Wz = g_ow16;
        bz = bp;
    }

    const int m0 = blockIdx.y * BM;
    const int n0 = blockIdx.x * BN;
    const int tid  = threadIdx.x;
    const int warp = tid >> 5, lane = tid & 31;
    const int wm = warp >> 2, wn = warp & 3;   // 4x4 warps, warp tile 32x32

    float acc[2][4][4];
#pragma unroll
    for (int mi = 0; mi < 2; mi++)
#pragma unroll
        for (int ni = 0; ni < 4; ni++)
#pragma unroll
            for (int r = 0; r < 4; r++) acc[mi][ni][r] = 0.f;

    // staging: thread -> one 16B chunk of A and one of B per stage
    const int srow = tid >> 2;          // 0..127
    const int sc16 = tid & 3;           // chunk within the 64B row
    const __half* srcA = &X [(size_t)(m0 + srow) * D_MODEL + sc16 * 8];
    const __half* srcB = &Wz[(size_t)(n0 + srow) * D_MODEL + sc16 * 8];
    const uint32_t dstA = (uint32_t)(srow * (PH * 2) + sc16 * 16);
    const uint32_t dstB = dstA + STG_MAT;

    // fragment lane addressing (bytes)
    const uint32_t aOff = ((lane & 15) * PH + (lane >> 4) * 8) * 2;
    const uint32_t bOff = ((((lane >> 4) << 3) + (lane & 7)) * PH + ((lane >> 3) & 1) * 8) * 2;

    auto issue_stage = [&](int s, int kt) {
        const uint32_t sb = smem_base + (uint32_t)s * STG_BYTES;
        cp_async16(sb + dstA, srcA + kt);
        cp_async16(sb + dstB, srcB + kt);
        cp_commit();
    };

    issue_stage(0, 0);
    issue_stage(1, BK);
    int kt_load = 2 * BK;

    int sc = 0;
    for (int kt = 0; kt < D_MODEL; kt += BK) {
        cp_wait<STAGES - 2>();
        __syncthreads();

        if (kt_load < D_MODEL) {
            int sl = sc + STAGES - 1; if (sl >= STAGES) sl -= STAGES;
            issue_stage(sl, kt_load);
            kt_load += BK;
        } else {
            cp_commit();   // keep wait_group count consistent
        }

        const uint32_t sA = smem_base + (uint32_t)sc * STG_BYTES;
        const uint32_t sB = sA + STG_MAT;

#pragma unroll
        for (int ks = 0; ks < 2; ks++) {            // two k16 steps per BK=32
            const uint32_t kb = ks * 16 * 2;        // byte offset of k-step
            uint32_t afr[2][4];
            uint32_t bfr[4][2];
#pragma unroll
            for (int mi = 0; mi < 2; mi++) {
                uint32_t addr = sA + (uint32_t)((wm * 32 + mi * 16) * PH * 2) + kb + aOff;
                ldsm_x4(afr[mi][0], afr[mi][1], afr[mi][2], afr[mi][3], addr);
            }
#pragma unroll
            for (int p = 0; p < 2; p++) {
                uint32_t addr = sB + (uint32_t)((wn * 32 + p * 16) * PH * 2) + kb + bOff;
                ldsm_x4(bfr[2 * p][0], bfr[2 * p][1], bfr[2 * p + 1][0], bfr[2 * p + 1][1], addr);
            }
#pragma unroll
            for (int mi = 0; mi < 2; mi++)
#pragma unroll
                for (int ni = 0; ni < 4; ni++)
                    mma_f16(acc[mi][ni], afr[mi], bfr[ni]);
        }
        sc++; if (sc == STAGES) sc = 0;
        __syncthreads();
    }

    // Epilogue
    const float qscale = (MODE == 0 && z == 0) ? 0.125f : 1.0f;
#pragma unroll
    for (int mi = 0; mi < 2; mi++) {
#pragma unroll
        for (int ni = 0; ni < 4; ni++) {
            int r0 = m0 + wm * 32 + mi * 16 + (lane >> 2);
            int c0 = n0 + wn * 32 + ni * 8 + (lane & 3) * 2;
#pragma unroll
            for (int half2i = 0; half2i < 2; half2i++) {
                int m = r0 + half2i * 8;
                float v0 = (acc[mi][ni][2 * half2i]     + bz[c0])     * qscale;
                float v1 = (acc[mi][ni][2 * half2i + 1] + bz[c0 + 1]) * qscale;
                if (MODE == 0) {
                    int b = m >> 12;
                    int l = m & 4095;
                    int w = l >> 7, rr = l & 127;
                    int h = c0 >> 6, d = c0 & 63;
                    size_t idx = ((((size_t)((b * NW + w) * NHEAD + h)) * WIN + rr) * HDIM) + d;
                    __half2 hv = __floats2half2_rn(v0, v1);
                    *(__half2*)&g_qkv16[(size_t)z * QKV_STRIDE + idx] = hv;
                } else {
                    *(float2*)&Yp[(size_t)m * D_MODEL + c0] = make_float2(v0, v1);
                }
            }
        }
    }
}

// ---------------------------------------------------------------------------
// fp16 windowed attention. One CTA (256 thr, 8 warps) per (b,w,h).
// Warp w owns rows w*16..w*16+15; softmax entirely in registers (quad shfl).
// smem (halves): sq[128][72], sk[128][72], sv[128][72], sp[128][136]
// ---------------------------------------------------------------------------
#define VP 72                      // q/k/v pitch (halves): 144B, conflict-free
#define PP 136                     // P pitch (halves): 272B, conflict-free
#define SQB 0
#define SKB (128 * VP * 2)         // 18432
#define SVB (2 * 128 * VP * 2)     // 36864
#define SPB (3 * 128 * VP * 2)     // 55296
#define ATTN_SMEM (SPB + 128 * PP * 2)   // 90112 bytes

__global__ __launch_bounds__(256) void attn_kernel() {
    extern __shared__ uint8_t smem[];
    const uint32_t sbase = (uint32_t)__cvta_generic_to_shared(smem);

    const int bid = blockIdx.x;
    const int h = bid & 15;
    const int w = (bid >> 4) & 31;
    const int b = bid >> 9;
    const size_t tile = ((size_t)((b * NW + w) * NHEAD + h)) * (WIN * HDIM);

    const __half* gq = g_qkv16 + tile;
    const __half* gk = g_qkv16 + QKV_STRIDE + tile;
    const __half* gv = g_qkv16 + 2 * QKV_STRIDE + tile;

    const int tid = threadIdx.x;
    const int warp = tid >> 5, lane = tid & 31;

    // ---- stage q,k,v via cp.async: 3*128 rows * 8 chunks = 3072 chunks ----
#pragma unroll
    for (int i = 0; i < 12; i++) {
        int ci = tid + i * 256;
        int mat = ci >> 10;               // 0=q 1=k 2=v
        int rc = ci & 1023;
        int row = rc >> 3;
        int c16 = rc & 7;
        const __half* src = (mat == 0) ? gq : (mat == 1) ? gk : gv;
        cp_async16(sbase + (uint32_t)(mat * (128 * VP * 2)) + row * (VP * 2) + c16 * 16,
                   src + row * HDIM + c16 * 8);
    }
    cp_commit();
    cp_wait<0>();
    __syncthreads();

    const uint32_t aOff = ((lane & 15) * VP + (lane >> 4) * 8) * 2;          // q rows
    const uint32_t bOff = ((((lane >> 4) << 3) + (lane & 7)) * VP + ((lane >> 3) & 1) * 8) * 2; // k rows
    const uint32_t aPOff = ((lane & 15) * PP + (lane >> 4) * 8) * 2;         // P rows
    const uint32_t vOff = ((((lane >> 3) & 1) * 8 + (lane & 7)) * VP + (lane >> 4) * 8) * 2;    // v trans

    const int mrow = warp * 16;

    // ---- QK^T: acc[16 ni][4], rows mrow..mrow+15 ----
    float acc[16][4];
#pragma unroll
    for (int ni = 0; ni < 16; ni++)
#pragma unroll
        for (int e = 0; e < 4; e++) acc[ni][e] = 0.f;

#pragma unroll
    for (int ks = 0; ks < 4; ks++) {              // 64 d = 4 k16 steps
        const uint32_t kb = ks * 16 * 2;
        uint32_t afr[4];
        ldsm_x4(afr[0], afr[1], afr[2], afr[3],
                sbase + SQB + (uint32_t)(mrow * VP * 2) + kb + aOff);
#pragma unroll
        for (int t = 0; t < 8; t++) {             // 128 j = 8 pairs of ni tiles
            uint32_t bfr[2][2];
            ldsm_x4(bfr[0][0], bfr[0][1], bfr[1][0], bfr[1][1],
                    sbase + SKB + (uint32_t)(t * 16 * VP * 2) + kb + bOff);
            mma_f16(acc[2 * t],     afr, bfr[0]);
            mma_f16(acc[2 * t + 1], afr, bfr[1]);
        }
    }

    // ---- softmax in registers (rows r0 = mrow+lane/4, r1 = r0+8) ----
    float mx0 = -1e30f, mx1 = -1e30f;
#pragma unroll
    for (int ni = 0; ni < 16; ni++) {
        mx0 = fmaxf(mx0, fmaxf(acc[ni][0], acc[ni][1]));
        mx1 = fmaxf(mx1, fmaxf(acc[ni][2], acc[ni][3]));
    }
    mx0 = fmaxf(mx0, __shfl_xor_sync(0xffffffff, mx0, 1));
    mx0 = fmaxf(mx0, __shfl_xor_sync(0xffffffff, mx0, 2));
    mx1 = fmaxf(mx1, __shfl_xor_sync(0xffffffff, mx1, 1));
    mx1 = fmaxf(mx1, __shfl_xor_sync(0xffffffff, mx1, 2));

    float sum0 = 0.f, sum1 = 0.f;
    const uint32_t spRow0 = sbase + SPB + (uint32_t)((mrow + (lane >> 2)) * PP + (lane & 3) * 2) * 2;
#pragma unroll
    for (int ni = 0; ni < 16; ni++) {
        float p0 = __expf(acc[ni][0] - mx0);
        float p1 = __expf(acc[ni][1] - mx0);
        float p2 = __expf(acc[ni][2] - mx1);
        float p3 = __expf(acc[ni][3] - mx1);
        sum0 += p0 + p1;
        sum1 += p2 + p3;
        __half2 h01 = __floats2half2_rn(p0, p1);
        __half2 h23 = __floats2half2_rn(p2, p3);
        asm volatile("st.shared.b32 [%0], %1;" :: "r"(spRow0 + ni * 16), "r"(*(uint32_t*)&h01));
        asm volatile("st.shared.b32 [%0], %1;" :: "r"(spRow0 + 8 * PP * 2 + ni * 16), "r"(*(uint32_t*)&h23));
    }
    sum0 += __shfl_xor_sync(0xffffffff, sum0, 1);
    sum0 += __shfl_xor_sync(0xffffffff, sum0, 2);
    sum1 += __shfl_xor_sync(0xffffffff, sum1, 1);
    sum1 += __shfl_xor_sync(0xffffffff, sum1, 2);
    const float inv0 = 1.f / sum0;
    const float inv1 = 1.f / sum1;
    __syncwarp();

    // ---- O = P @ V: 8 ksteps of k16 over j; 8 ni tiles over d=64 ----
    float oacc[8][4];
#pragma unroll
    for (int n = 0; n < 8; n++)
#pragma unroll
        for (int e = 0; e < 4; e++) oacc[n][e] = 0.f;

#pragma unroll
    for (int ks = 0; ks < 8; ks++) {              // 128 j
        uint32_t afr[4];
        ldsm_x4(afr[0], afr[1], afr[2], afr[3],
                sbase + SPB + (uint32_t)(mrow * PP * 2) + ks * 16 * 2 + aPOff);
#pragma unroll
        for (int dt = 0; dt < 4; dt++) {          // 64 d = 4 x (two 8-wide tiles)
            uint32_t bfr[2][2];
            ldsm_x4_t(bfr[0][0], bfr[0][1], bfr[1][0], bfr[1][1],
                      sbase + SVB + (uint32_t)(ks * 16 * VP * 2) + dt * 16 * 2 + vOff);
            mma_f16(oacc[2 * dt],     afr, bfr[0]);
            mma_f16(oacc[2 * dt + 1], afr, bfr[1]);
        }
    }

    // ---- epilogue: normalize, store half to g_attn16 ----
    const int r0 = mrow + (lane >> 2);
    const size_t gb0 = ((size_t)b * SEQ + (size_t)w * WIN + r0) * D_MODEL + h * HDIM;
    const size_t gb1 = gb0 + 8ull * D_MODEL;
#pragma unroll
    for (int n = 0; n < 8; n++) {
        const int c0 = n * 8 + (lane & 3) * 2;
        __half2 h0 = __floats2half2_rn(oacc[n][0] * inv0, oacc[n][1] * inv0);
        __half2 h1 = __floats2half2_rn(oacc[n][2] * inv1, oacc[n][3] * inv1);
        *(__half2*)&g_attn16[gb0 + c0] = h0;
        *(__half2*)&g_attn16[gb1 + c0] = h1;
    }
}

// ---------------------------------------------------------------------------
extern "C" void kernel_launch(void* const* d_in, const int* in_sizes, int n_in,
                              void* d_out, int out_size) {
    const float* q   = (const float*)d_in[0];
    const float* k   = (const float*)d_in[1];
    const float* v   = (const float*)d_in[2];
    const float* ipw = (const float*)d_in[3];
    const float* ipb = (const float*)d_in[4];
    const float* ow  = (const float*)d_in[5];
    const float* ob  = (const float*)d_in[6];
    float* out = (float*)d_out;

    cudaFuncSetAttribute(gemm_f16<0>, cudaFuncAttributeMaxDynamicSharedMemorySize, GEMM_SMEM);
    cudaFuncSetAttribute(gemm_f16<1>, cudaFuncAttributeMaxDynamicSharedMemorySize, GEMM_SMEM);
    cudaFuncSetAttribute(attn_kernel, cudaFuncAttributeMaxDynamicSharedMemorySize, ATTN_SMEM);

    __half* x16;  cudaGetSymbolAddress((void**)&x16,  g_x16);
    __half* w16;  cudaGetSymbolAddress((void**)&w16,  g_w16);
    __half* ow16; cudaGetSymbolAddress((void**)&ow16, g_ow16);

    // 0) fp16 prepass (pure bandwidth)
    cvt_half<<<2048, 256>>>(q, x16,                  M_TOTAL * D_MODEL / 4);
    cvt_half<<<2048, 256>>>(k, x16 + QKV_STRIDE,     M_TOTAL * D_MODEL / 4);
    cvt_half<<<2048, 256>>>(v, x16 + 2 * QKV_STRIDE, M_TOTAL * D_MODEL / 4);
    cvt_half<<<1024, 256>>>(ipw, w16,                3 * D_MODEL * D_MODEL / 4);
    cvt_half<<<512,  256>>>(ow,  ow16,               D_MODEL * D_MODEL / 4);

    // 1) QKV projection (Q scaled by 1/8 in epilogue)
    dim3 g0(D_MODEL / BN, M_TOTAL / BM, 3);
    gemm_f16<0><<<g0, 512, GEMM_SMEM>>>(ipb, nullptr);

    // 2) Windowed attention: 2048 blocks
    attn_kernel<<<BATCH * NW * NHEAD, 256, ATTN_SMEM>>>();

    // 3) Output projection
    dim3 g1(D_MODEL / BN, M_TOTAL / BM, 1);
    gemm_f16<1><<<g1, 512, GEMM_SMEM>>>(ob, out);
}

// round 11
// speedup vs baseline: 3.0749x; 1.0485x over previous
#include <cuda_runtime.h>
#include <cuda_fp16.h>
#include <cstdint>
#include <cstdio>

#define D_MODEL 1024
#define NHEAD   16
#define HDIM    64
#define WIN     128
#define BATCH   4
#define SEQ     4096
#define NW      (SEQ / WIN)            // 32
#define M_TOTAL (BATCH * SEQ)          // 16384
#define QKV_STRIDE ((size_t)M_TOTAL * D_MODEL)  // 16777216

// Scratch (allocation-free rule: device globals)
__device__ __half g_x16[3ull * M_TOTAL * D_MODEL];    // fp16 q,k,v inputs
__device__ __half g_w16[3ull * D_MODEL * D_MODEL];    // fp16 in_proj_w
__device__ __half g_ow16[(size_t)D_MODEL * D_MODEL];  // fp16 out_w
__device__ __half g_qkv16[3ull * M_TOTAL * D_MODEL];  // fp16 attention tiles (Q pre-scaled)
__device__ __half g_attn16[(size_t)M_TOTAL * D_MODEL];// fp16 attention output

// ---------------------------------------------------------------------------
// helpers (generic-target ISA only; tcgen05 rejected by harness ptxas sm_103)
// ---------------------------------------------------------------------------
__device__ __forceinline__ void mma_f16(float c[4], const uint32_t a[4], const uint32_t b[2]) {
    asm volatile(
        "mma.sync.aligned.m16n8k16.row.col.f32.f16.f16.f32 "
        "{%0,%1,%2,%3}, {%4,%5,%6,%7}, {%8,%9}, {%0,%1,%2,%3};\n"
        : "+f"(c[0]), "+f"(c[1]), "+f"(c[2]), "+f"(c[3])
        : "r"(a[0]), "r"(a[1]), "r"(a[2]), "r"(a[3]), "r"(b[0]), "r"(b[1]));
}

__device__ __forceinline__ void ldsm_x4(uint32_t& r0, uint32_t& r1, uint32_t& r2, uint32_t& r3,
                                        uint32_t saddr) {
    asm volatile("ldmatrix.sync.aligned.m8n8.x4.shared.b16 {%0,%1,%2,%3}, [%4];"
                 : "=r"(r0), "=r"(r1), "=r"(r2), "=r"(r3) : "r"(saddr));
}
__device__ __forceinline__ void ldsm_x4_t(uint32_t& r0, uint32_t& r1, uint32_t& r2, uint32_t& r3,
                                          uint32_t saddr) {
    asm volatile("ldmatrix.sync.aligned.m8n8.x4.trans.shared.b16 {%0,%1,%2,%3}, [%4];"
                 : "=r"(r0), "=r"(r1), "=r"(r2), "=r"(r3) : "r"(saddr));
}

__device__ __forceinline__ void cp_async16(uint32_t dst, const void* src) {
    asm volatile("cp.async.cg.shared.global [%0], [%1], 16;\n" :: "r"(dst), "l"(src));
}
__device__ __forceinline__ void cp_commit() { asm volatile("cp.async.commit_group;\n" ::: "memory"); }
template <int N>
__device__ __forceinline__ void cp_wait() { asm volatile("cp.async.wait_group %0;\n" :: "n"(N) : "memory"); }

// ---------------------------------------------------------------------------
// Prepass: fp32 -> fp16, MLP=4 (4 independent loads in flight per iteration)
// ---------------------------------------------------------------------------
__device__ __forceinline__ uint2 cvt4(float4 v) {
    __half2 lo = __floats2half2_rn(v.x, v.y);
    __half2 hi = __floats2half2_rn(v.z, v.w);
    return make_uint2(*(uint32_t*)&lo, *(uint32_t*)&hi);
}

__global__ __launch_bounds__(256) void cvt3(const float* __restrict__ q,
                                            const float* __restrict__ k,
                                            const float* __restrict__ v) {
    const int z = blockIdx.y;
    const float* src = (z == 0) ? q : (z == 1) ? k : v;
    __half* dst = g_x16 + (size_t)z * QKV_STRIDE;
    const int n4 = M_TOTAL * D_MODEL / 4;
    const int stride = gridDim.x * 256;
    int i = blockIdx.x * 256 + threadIdx.x;
    for (; i + 3 * stride < n4; i += 4 * stride) {
        float4 v0 = *(const float4*)&src[4 * i];
        float4 v1 = *(const float4*)&src[4 * (i + stride)];
        float4 v2 = *(const float4*)&src[4 * (i + 2 * stride)];
        float4 v3 = *(const float4*)&src[4 * (i + 3 * stride)];
        *(uint2*)&dst[4 * i]                = cvt4(v0);
        *(uint2*)&dst[4 * (i + stride)]     = cvt4(v1);
        *(uint2*)&dst[4 * (i + 2 * stride)] = cvt4(v2);
        *(uint2*)&dst[4 * (i + 3 * stride)] = cvt4(v3);
    }
    for (; i < n4; i += stride) *(uint2*)&dst[4 * i] = cvt4(*(const float4*)&src[4 * i]);
}

__global__ __launch_bounds__(256) void cvt_half(const float* __restrict__ src,
                                                __half* __restrict__ dst, int n4) {
    const int stride = gridDim.x * 256;
    int i = blockIdx.x * 256 + threadIdx.x;
    for (; i + 3 * stride < n4; i += 4 * stride) {
        float4 v0 = *(const float4*)&src[4 * i];
        float4 v1 = *(const float4*)&src[4 * (i + stride)];
        float4 v2 = *(const float4*)&src[4 * (i + 2 * stride)];
        float4 v3 = *(const float4*)&src[4 * (i + 3 * stride)];
        *(uint2*)&dst[4 * i]                = cvt4(v0);
        *(uint2*)&dst[4 * (i + stride)]     = cvt4(v1);
        *(uint2*)&dst[4 * (i + 2 * stride)] = cvt4(v2);
        *(uint2*)&dst[4 * (i + 3 * stride)] = cvt4(v3);
    }
    for (; i < n4; i += stride) *(uint2*)&dst[4 * i] = cvt4(*(const float4*)&src[4 * i]);
}

// ---------------------------------------------------------------------------
// fp16 GEMM: Y[M,N] = X[M,K] @ W[N,K]^T + bias   (TN, both K-contiguous)
// Block tile 128x256, BK=32, 512 threads (16 warps as 4x4), warp tile 32x64.
// 3-stage cp.async pipeline. Inner loop: 6 LDSM.x4 + 16 HMMA per k16 step.
// ---------------------------------------------------------------------------
#define BM 128
#define BN 256
#define BK 32
#define PH 40                                 // halves pitch: 80B, conflict-free
#define STG_A (128 * PH * 2)                  // 10240 B
#define STG_B (256 * PH * 2)                  // 20480 B
#define STG_BYTES (STG_A + STG_B)             // 30720 B
#define STAGES 3
#define GEMM_SMEM (STAGES * STG_BYTES)        // 92160 B

template <int MODE>
__global__ __launch_bounds__(512) void gemm_f16(
    const float* __restrict__ bp, float* __restrict__ Yp)
{
    extern __shared__ uint8_t smem[];
    const uint32_t smem_base = (uint32_t)__cvta_generic_to_shared(smem);

    const int z = blockIdx.z;
    const __half* X;
    const __half* Wz;
    const float* bz;
    if (MODE == 0) {
        X  = g_x16 + (size_t)z * QKV_STRIDE;
        Wz = g_w16 + (size_t)z * D_MODEL * D_MODEL;
        bz = bp + z * D_MODEL;
    } else {
        X  = g_attn16;
        Wz = g_ow16;
        bz = bp;
    }

    const int m0 = blockIdx.y * BM;
    const int n0 = blockIdx.x * BN;
    const int tid  = threadIdx.x;
    const int warp = tid >> 5, lane = tid & 31;
    const int wm = warp >> 2, wn = warp & 3;   // 4x4 warps, warp tile 32x64

    float acc[2][8][4];
#pragma unroll
    for (int mi = 0; mi < 2; mi++)
#pragma unroll
        for (int ni = 0; ni < 8; ni++)
#pragma unroll
            for (int r = 0; r < 4; r++) acc[mi][ni][r] = 0.f;

    // staging: 1536 x 16B chunks per stage, 3 per thread
    uint32_t dsts[3];
    const __half* srcs[3];
#pragma unroll
    for (int i = 0; i < 3; i++) {
        int ci = tid + i * 512;
        if (ci < 512) {
            int row = ci >> 2, c16 = ci & 3;
            dsts[i] = (uint32_t)(row * (PH * 2) + c16 * 16);
            srcs[i] = &X[(size_t)(m0 + row) * D_MODEL + c16 * 8];
        } else {
            int bi = ci - 512;
            int row = bi >> 2, c16 = bi & 3;
            dsts[i] = (uint32_t)(STG_A + row * (PH * 2) + c16 * 16);
            srcs[i] = &Wz[(size_t)(n0 + row) * D_MODEL + c16 * 8];
        }
    }

    // fragment lane addressing (bytes)
    const uint32_t aOff = ((lane & 15) * PH + (lane >> 4) * 8) * 2;
    const uint32_t bOff = ((((lane >> 4) << 3) + (lane & 7)) * PH + ((lane >> 3) & 1) * 8) * 2;

    auto issue_stage = [&](int s, int kt) {
        const uint32_t sb = smem_base + (uint32_t)s * STG_BYTES;
#pragma unroll
        for (int i = 0; i < 3; i++) cp_async16(sb + dsts[i], srcs[i] + kt);
        cp_commit();
    };

    issue_stage(0, 0);
    issue_stage(1, BK);
    int kt_load = 2 * BK;

    int sc = 0;
    for (int kt = 0; kt < D_MODEL; kt += BK) {
        cp_wait<STAGES - 2>();
        __syncthreads();

        if (kt_load < D_MODEL) {
            int sl = sc + STAGES - 1; if (sl >= STAGES) sl -= STAGES;
            issue_stage(sl, kt_load);
            kt_load += BK;
        } else {
            cp_commit();   // keep wait_group count consistent
        }

        const uint32_t sA = smem_base + (uint32_t)sc * STG_BYTES;
        const uint32_t sB = sA + STG_A;

#pragma unroll
        for (int ks = 0; ks < 2; ks++) {            // two k16 steps per BK=32
            const uint32_t kb = ks * 32;            // byte offset of k-step
            uint32_t afr[2][4];
            uint32_t bfr[8][2];
#pragma unroll
            for (int mi = 0; mi < 2; mi++) {
                uint32_t addr = sA + (uint32_t)((wm * 32 + mi * 16) * PH * 2) + kb + aOff;
                ldsm_x4(afr[mi][0], afr[mi][1], afr[mi][2], afr[mi][3], addr);
            }
#pragma unroll
            for (int p = 0; p < 4; p++) {
                uint32_t addr = sB + (uint32_t)((wn * 64 + p * 16) * PH * 2) + kb + bOff;
                ldsm_x4(bfr[2 * p][0], bfr[2 * p][1], bfr[2 * p + 1][0], bfr[2 * p + 1][1], addr);
            }
#pragma unroll
            for (int mi = 0; mi < 2; mi++)
#pragma unroll
                for (int ni = 0; ni < 8; ni++)
                    mma_f16(acc[mi][ni], afr[mi], bfr[ni]);
        }
        sc++; if (sc == STAGES) sc = 0;
        __syncthreads();
    }

    // Epilogue
    const float qscale = (MODE == 0 && z == 0) ? 0.125f : 1.0f;
#pragma unroll
    for (int mi = 0; mi < 2; mi++) {
#pragma unroll
        for (int ni = 0; ni < 8; ni++) {
            int r0 = m0 + wm * 32 + mi * 16 + (lane >> 2);
            int c0 = n0 + wn * 64 + ni * 8 + (lane & 3) * 2;
#pragma unroll
            for (int half2i = 0; half2i < 2; half2i++) {
                int m = r0 + half2i * 8;
                float v0 = (acc[mi][ni][2 * half2i]     + bz[c0])     * qscale;
                float v1 = (acc[mi][ni][2 * half2i + 1] + bz[c0 + 1]) * qscale;
                if (MODE == 0) {
                    int b = m >> 12;
                    int l = m & 4095;
                    int w = l >> 7, rr = l & 127;
                    int h = c0 >> 6, d = c0 & 63;
                    size_t idx = ((((size_t)((b * NW + w) * NHEAD + h)) * WIN + rr) * HDIM) + d;
                    __half2 hv = __floats2half2_rn(v0, v1);
                    *(__half2*)&g_qkv16[(size_t)z * QKV_STRIDE + idx] = hv;
                } else {
                    *(float2*)&Yp[(size_t)m * D_MODEL + c0] = make_float2(v0, v1);
                }
            }
        }
    }
}

// ---------------------------------------------------------------------------
// fp16 windowed attention. One CTA (256 thr, 8 warps) per (b,w,h).
// Warp w owns rows w*16..w*16+15; softmax entirely in registers (quad shfl).
// smem (halves): sq[128][72], sk[128][72], sv[128][72], sp[128][136]
// ---------------------------------------------------------------------------
#define VP 72                      // q/k/v pitch (halves): 144B, conflict-free
#define PP 136                     // P pitch (halves): 272B, conflict-free
#define SQB 0
#define SKB (128 * VP * 2)         // 18432
#define SVB (2 * 128 * VP * 2)     // 36864
#define SPB (3 * 128 * VP * 2)     // 55296
#define ATTN_SMEM (SPB + 128 * PP * 2)   // 90112 bytes

__global__ __launch_bounds__(256) void attn_kernel() {
    extern __shared__ uint8_t smem[];
    const uint32_t sbase = (uint32_t)__cvta_generic_to_shared(smem);

    const int bid = blockIdx.x;
    const int h = bid & 15;
    const int w = (bid >> 4) & 31;
    const int b = bid >> 9;
    const size_t tile = ((size_t)((b * NW + w) * NHEAD + h)) * (WIN * HDIM);

    const __half* gq = g_qkv16 + tile;
    const __half* gk = g_qkv16 + QKV_STRIDE + tile;
    const __half* gv = g_qkv16 + 2 * QKV_STRIDE + tile;

    const int tid = threadIdx.x;
    const int warp = tid >> 5, lane = tid & 31;

    // ---- stage q,k,v via cp.async ----
#pragma unroll
    for (int i = 0; i < 12; i++) {
        int ci = tid + i * 256;
        int mat = ci >> 10;               // 0=q 1=k 2=v
        int rc = ci & 1023;
        int row = rc >> 3;
        int c16 = rc & 7;
        const __half* src = (mat == 0) ? gq : (mat == 1) ? gk : gv;
        cp_async16(sbase + (uint32_t)(mat * (128 * VP * 2)) + row * (VP * 2) + c16 * 16,
                   src + row * HDIM + c16 * 8);
    }
    cp_commit();
    cp_wait<0>();
    __syncthreads();

    const uint32_t aOff = ((lane & 15) * VP + (lane >> 4) * 8) * 2;          // q rows
    const uint32_t bOff = ((((lane >> 4) << 3) + (lane & 7)) * VP + ((lane >> 3) & 1) * 8) * 2; // k rows
    const uint32_t aPOff = ((lane & 15) * PP + (lane >> 4) * 8) * 2;         // P rows
    const uint32_t vOff = ((((lane >> 3) & 1) * 8 + (lane & 7)) * VP + (lane >> 4) * 8) * 2;    // v trans

    const int mrow = warp * 16;

    // ---- QK^T: acc[16 ni][4], rows mrow..mrow+15 ----
    float acc[16][4];
#pragma unroll
    for (int ni = 0; ni < 16; ni++)
#pragma unroll
        for (int e = 0; e < 4; e++) acc[ni][e] = 0.f;

#pragma unroll
    for (int ks = 0; ks < 4; ks++) {              // 64 d = 4 k16 steps
        const uint32_t kb = ks * 32;
        uint32_t afr[4];
        ldsm_x4(afr[0], afr[1], afr[2], afr[3],
                sbase + SQB + (uint32_t)(mrow * VP * 2) + kb + aOff);
#pragma unroll
        for (int t = 0; t < 8; t++) {             // 128 j = 8 pairs of ni tiles
            uint32_t bfr[2][2];
            ldsm_x4(bfr[0][0], bfr[0][1], bfr[1][0], bfr[1][1],
                    sbase + SKB + (uint32_t)(t * 16 * VP * 2) + kb + bOff);
            mma_f16(acc[2 * t],     afr, bfr[0]);
            mma_f16(acc[2 * t + 1], afr, bfr[1]);
        }
    }

    // ---- softmax in registers (rows r0 = mrow+lane/4, r1 = r0+8) ----
    float mx0 = -1e30f, mx1 = -1e30f;
#pragma unroll
    for (int ni = 0; ni < 16; ni++) {
        mx0 = fmaxf(mx0, fmaxf(acc[ni][0], acc[ni][1]));
        mx1 = fmaxf(mx1, fmaxf(acc[ni][2], acc[ni][3]));
    }
    mx0 = fmaxf(mx0, __shfl_xor_sync(0xffffffff, mx0, 1));
    mx0 = fmaxf(mx0, __shfl_xor_sync(0xffffffff, mx0, 2));
    mx1 = fmaxf(mx1, __shfl_xor_sync(0xffffffff, mx1, 1));
    mx1 = fmaxf(mx1, __shfl_xor_sync(0xffffffff, mx1, 2));

    float sum0 = 0.f, sum1 = 0.f;
    const uint32_t spRow0 = sbase + SPB + (uint32_t)((mrow + (lane >> 2)) * PP + (lane & 3) * 2) * 2;
#pragma unroll
    for (int ni = 0; ni < 16; ni++) {
        float p0 = __expf(acc[ni][0] - mx0);
        float p1 = __expf(acc[ni][1] - mx0);
        float p2 = __expf(acc[ni][2] - mx1);
        float p3 = __expf(acc[ni][3] - mx1);
        sum0 += p0 + p1;
        sum1 += p2 + p3;
        __half2 h01 = __floats2half2_rn(p0, p1);
        __half2 h23 = __floats2half2_rn(p2, p3);
        asm volatile("st.shared.b32 [%0], %1;" :: "r"(spRow0 + ni * 16), "r"(*(uint32_t*)&h01));
        asm volatile("st.shared.b32 [%0], %1;" :: "r"(spRow0 + 8 * PP * 2 + ni * 16), "r"(*(uint32_t*)&h23));
    }
    sum0 += __shfl_xor_sync(0xffffffff, sum0, 1);
    sum0 += __shfl_xor_sync(0xffffffff, sum0, 2);
    sum1 += __shfl_xor_sync(0xffffffff, sum1, 1);
    sum1 += __shfl_xor_sync(0xffffffff, sum1, 2);
    const float inv0 = 1.f / sum0;
    const float inv1 = 1.f / sum1;
    __syncwarp();

    // ---- O = P @ V ----
    float oacc[8][4];
#pragma unroll
    for (int n = 0; n < 8; n++)
#pragma unroll
        for (int e = 0; e < 4; e++) oacc[n][e] = 0.f;

#pragma unroll
    for (int ks = 0; ks < 8; ks++) {              // 128 j
        uint32_t afr[4];
        ldsm_x4(afr[0], afr[1], afr[2], afr[3],
                sbase + SPB + (uint32_t)(mrow * PP * 2) + ks * 32 + aPOff);
#pragma unroll
        for (int dt = 0; dt < 4; dt++) {          // 64 d
            uint32_t bfr[2][2];
            ldsm_x4_t(bfr[0][0], bfr[0][1], bfr[1][0], bfr[1][1],
                      sbase + SVB + (uint32_t)(ks * 16 * VP * 2) + dt * 32 + vOff);
            mma_f16(oacc[2 * dt],     afr, bfr[0]);
            mma_f16(oacc[2 * dt + 1], afr, bfr[1]);
        }
    }

    // ---- epilogue: normalize, store half to g_attn16 ----
    const int r0 = mrow + (lane >> 2);
    const size_t gb0 = ((size_t)b * SEQ + (size_t)w * WIN + r0) * D_MODEL + h * HDIM;
    const size_t gb1 = gb0 + 8ull * D_MODEL;
#pragma unroll
    for (int n = 0; n < 8; n++) {
        const int c0 = n * 8 + (lane & 3) * 2;
        __half2 h0 = __floats2half2_rn(oacc[n][0] * inv0, oacc[n][1] * inv0);
        __half2 h1 = __floats2half2_rn(oacc[n][2] * inv1, oacc[n][3] * inv1);
        *(__half2*)&g_attn16[gb0 + c0] = h0;
        *(__half2*)&g_attn16[gb1 + c0] = h1;
    }
}

// ---------------------------------------------------------------------------
extern "C" void kernel_launch(void* const* d_in, const int* in_sizes, int n_in,
                              void* d_out, int out_size) {
    const float* q   = (const float*)d_in[0];
    const float* k   = (const float*)d_in[1];
    const float* v   = (const float*)d_in[2];
    const float* ipw = (const float*)d_in[3];
    const float* ipb = (const float*)d_in[4];
    const float* ow  = (const float*)d_in[5];
    const float* ob  = (const float*)d_in[6];
    float* out = (float*)d_out;

    cudaFuncSetAttribute(gemm_f16<0>, cudaFuncAttributeMaxDynamicSharedMemorySize, GEMM_SMEM);
    cudaFuncSetAttribute(gemm_f16<1>, cudaFuncAttributeMaxDynamicSharedMemorySize, GEMM_SMEM);
    cudaFuncSetAttribute(attn_kernel, cudaFuncAttributeMaxDynamicSharedMemorySize, ATTN_SMEM);

    __half* w16;  cudaGetSymbolAddress((void**)&w16,  g_w16);
    __half* ow16; cudaGetSymbolAddress((void**)&ow16, g_ow16);

    // 0) fp16 prepass (bandwidth, MLP=4)
    dim3 gc(1024, 3);
    cvt3<<<gc, 256>>>(q, k, v);
    cvt_half<<<512, 256>>>(ipw, w16, 3 * D_MODEL * D_MODEL / 4);
    cvt_half<<<256, 256>>>(ow,  ow16,    D_MODEL * D_MODEL / 4);

    // 1) QKV projection (Q scaled by 1/8 in epilogue)
    dim3 g0(D_MODEL / BN, M_TOTAL / BM, 3);
    gemm_f16<0><<<g0, 512, GEMM_SMEM>>>(ipb, nullptr);

    // 2) Windowed attention: 2048 blocks
    attn_kernel<<<BATCH * NW * NHEAD, 256, ATTN_SMEM>>>();

    // 3) Output projection
    dim3 g1(D_MODEL / BN, M_TOTAL / BM, 1);
    gemm_f16<1><<<g1, 512, GEMM_SMEM>>>(ob, out);
}

// round 14
// speedup vs baseline: 3.7258x; 1.2117x over previous
#include <cuda_runtime.h>
#include <cuda_fp16.h>
#include <cstdint>
#include <cstdio>

#define D_MODEL 1024
#define NHEAD   16
#define HDIM    64
#define WIN     128
#define BATCH   4
#define SEQ     4096
#define NW      (SEQ / WIN)            // 32
#define M_TOTAL (BATCH * SEQ)          // 16384
#define QKV_STRIDE ((size_t)M_TOTAL * D_MODEL)  // 16777216

// Scratch (allocation-free rule: device globals)
__device__ __half g_x16[3ull * M_TOTAL * D_MODEL];    // fp16 q,k,v inputs
__device__ __half g_w16[3ull * D_MODEL * D_MODEL];    // fp16 in_proj_w
__device__ __half g_ow16[(size_t)D_MODEL * D_MODEL];  // fp16 out_w
__device__ __half g_qkv16[3ull * M_TOTAL * D_MODEL];  // fp16 attention tiles (Q pre-scaled)
__device__ __half g_attn16[(size_t)M_TOTAL * D_MODEL];// fp16 attention output

// ---------------------------------------------------------------------------
// helpers (generic-target ISA only; tcgen05 rejected by harness ptxas sm_103)
// ---------------------------------------------------------------------------
__device__ __forceinline__ void mma_f16(float c[4], const uint32_t a[4], const uint32_t b[2]) {
    asm volatile(
        "mma.sync.aligned.m16n8k16.row.col.f32.f16.f16.f32 "
        "{%0,%1,%2,%3}, {%4,%5,%6,%7}, {%8,%9}, {%0,%1,%2,%3};\n"
        : "+f"(c[0]), "+f"(c[1]), "+f"(c[2]), "+f"(c[3])
        : "r"(a[0]), "r"(a[1]), "r"(a[2]), "r"(a[3]), "r"(b[0]), "r"(b[1]));
}

__device__ __forceinline__ void ldsm_x4(uint32_t& r0, uint32_t& r1, uint32_t& r2, uint32_t& r3,
                                        uint32_t saddr) {
    asm volatile("ldmatrix.sync.aligned.m8n8.x4.shared.b16 {%0,%1,%2,%3}, [%4];"
                 : "=r"(r0), "=r"(r1), "=r"(r2), "=r"(r3) : "r"(saddr));
}
__device__ __forceinline__ void ldsm_x4_t(uint32_t& r0, uint32_t& r1, uint32_t& r2, uint32_t& r3,
                                          uint32_t saddr) {
    asm volatile("ldmatrix.sync.aligned.m8n8.x4.trans.shared.b16 {%0,%1,%2,%3}, [%4];"
                 : "=r"(r0), "=r"(r1), "=r"(r2), "=r"(r3) : "r"(saddr));
}

__device__ __forceinline__ void cp_async16(uint32_t dst, const void* src) {
    asm volatile("cp.async.cg.shared.global [%0], [%1], 16;\n" :: "r"(dst), "l"(src));
}
__device__ __forceinline__ void cp_commit() { asm volatile("cp.async.commit_group;\n" ::: "memory"); }
template <int N>
__device__ __forceinline__ void cp_wait() { asm volatile("cp.async.wait_group %0;\n" :: "n"(N) : "memory"); }

// ---------------------------------------------------------------------------
// Prepass: fp32 -> fp16, MLP=4
// ---------------------------------------------------------------------------
__device__ __forceinline__ uint2 cvt4(float4 v) {
    __half2 lo = __floats2half2_rn(v.x, v.y);
    __half2 hi = __floats2half2_rn(v.z, v.w);
    return make_uint2(*(uint32_t*)&lo, *(uint32_t*)&hi);
}

__global__ __launch_bounds__(256) void cvt3(const float* __restrict__ q,
                                            const float* __restrict__ k,
                                            const float* __restrict__ v) {
    const int z = blockIdx.y;
    const float* src = (z == 0) ? q : (z == 1) ? k : v;
    __half* dst = g_x16 + (size_t)z * QKV_STRIDE;
    const int n4 = M_TOTAL * D_MODEL / 4;
    const int stride = gridDim.x * 256;
    int i = blockIdx.x * 256 + threadIdx.x;
    for (; i + 3 * stride < n4; i += 4 * stride) {
        float4 v0 = *(const float4*)&src[4 * i];
        float4 v1 = *(const float4*)&src[4 * (i + stride)];
        float4 v2 = *(const float4*)&src[4 * (i + 2 * stride)];
        float4 v3 = *(const float4*)&src[4 * (i + 3 * stride)];
        *(uint2*)&dst[4 * i]                = cvt4(v0);
        *(uint2*)&dst[4 * (i + stride)]     = cvt4(v1);
        *(uint2*)&dst[4 * (i + 2 * stride)] = cvt4(v2);
        *(uint2*)&dst[4 * (i + 3 * stride)] = cvt4(v3);
    }
    for (; i < n4; i += stride) *(uint2*)&dst[4 * i] = cvt4(*(const float4*)&src[4 * i]);
}

__global__ __launch_bounds__(256) void cvt_half(const float* __restrict__ src,
                                                __half* __restrict__ dst, int n4) {
    const int stride = gridDim.x * 256;
    int i = blockIdx.x * 256 + threadIdx.x;
    for (; i + 3 * stride < n4; i += 4 * stride) {
        float4 v0 = *(const float4*)&src[4 * i];
        float4 v1 = *(const float4*)&src[4 * (i + stride)];
        float4 v2 = *(const float4*)&src[4 * (i + 2 * stride)];
        float4 v3 = *(const float4*)&src[4 * (i + 3 * stride)];
        *(uint2*)&dst[4 * i]                = cvt4(v0);
        *(uint2*)&dst[4 * (i + stride)]     = cvt4(v1);
        *(uint2*)&dst[4 * (i + 2 * stride)] = cvt4(v2);
        *(uint2*)&dst[4 * (i + 3 * stride)] = cvt4(v3);
    }
    for (; i < n4; i += stride) *(uint2*)&dst[4 * i] = cvt4(*(const float4*)&src[4 * i]);
}

// ---------------------------------------------------------------------------
// fp16 GEMM: Y[M,N] = X[M,K] @ W[N,K]^T + bias   (TN, both K-contiguous)
// 256 threads (8 warps as 4x2), warp tile 32x64, block tile 128x128, BK=32.
// 3-stage cp.async pipeline, ONE barrier per K-tile, 2 CTAs/SM resident.
// ---------------------------------------------------------------------------
#define BM 128
#define BN 128
#define BK 32
#define PH 40                                 // halves pitch: 80B, conflict-free
#define STG_MAT (128 * PH * 2)                // 10240 B per matrix
#define STG_BYTES (2 * STG_MAT)               // 20480 B per stage
#define STAGES 3
#define GEMM_SMEM (STAGES * STG_BYTES)        // 61440 B per CTA (2 CTAs = 120 KB)

template <int MODE>
__global__ __launch_bounds__(256, 2) void gemm_f16(
    const float* __restrict__ bp, float* __restrict__ Yp)
{
    extern __shared__ uint8_t smem[];
    const uint32_t smem_base = (uint32_t)__cvta_generic_to_shared(smem);

    const int z = blockIdx.z;
    const __half* X;
    const __half* Wz;
    const float* bz;
    if (MODE == 0) {
        X  = g_x16 + (size_t)z * QKV_STRIDE;
        Wz = g_w16 + (size_t)z * D_MODEL * D_MODEL;
        bz = bp + z * D_MODEL;
    } else {
        X  = g_attn16;
        Wz = g_ow16;
        bz = bp;
    }

    const int m0 = blockIdx.y * BM;
    const int n0 = blockIdx.x * BN;
    const int tid  = threadIdx.x;
    const int warp = tid >> 5, lane = tid & 31;
    const int wm = warp >> 1, wn = warp & 1;   // 4x2 warps, warp tile 32x64

    float acc[2][8][4];
#pragma unroll
    for (int mi = 0; mi < 2; mi++)
#pragma unroll
        for (int ni = 0; ni < 8; ni++)
#pragma unroll
            for (int r = 0; r < 4; r++) acc[mi][ni][r] = 0.f;

    // staging: 1024 x 16B chunks per stage, 4 per thread (A then B)
    uint32_t dsts[4];
    const __half* srcs[4];
#pragma unroll
    for (int i = 0; i < 4; i++) {
        int ci = tid + i * 256;
        int mat = ci >> 9;                  // 0=A, 1=B
        int rc = ci & 511;
        int row = rc >> 2, c16 = rc & 3;
        dsts[i] = (uint32_t)(mat * STG_MAT + row * (PH * 2) + c16 * 16);
        srcs[i] = (mat == 0) ? &X [(size_t)(m0 + row) * D_MODEL + c16 * 8]
                             : &Wz[(size_t)(n0 + row) * D_MODEL + c16 * 8];
    }

    // fragment lane addressing (bytes)
    const uint32_t aOff = ((lane & 15) * PH + (lane >> 4) * 8) * 2;
    const uint32_t bOff = ((((lane >> 4) << 3) + (lane & 7)) * PH + ((lane >> 3) & 1) * 8) * 2;

    auto issue_stage = [&](int s, int kt) {
        const uint32_t sb = smem_base + (uint32_t)s * STG_BYTES;
#pragma unroll
        for (int i = 0; i < 4; i++) cp_async16(sb + dsts[i], srcs[i] + kt);
        cp_commit();
    };

    issue_stage(0, 0);
    issue_stage(1, BK);
    int kt_load = 2 * BK;

    int sc = 0;
    for (int kt = 0; kt < D_MODEL; kt += BK) {
        cp_wait<STAGES - 2>();
        __syncthreads();   // stage sc ready for all; all warps done with slot (sc+2)%3

        if (kt_load < D_MODEL) {
            int sl = sc + STAGES - 1; if (sl >= STAGES) sl -= STAGES;
            issue_stage(sl, kt_load);
            kt_load += BK;
        } else {
            cp_commit();   // keep wait_group count consistent
        }

        const uint32_t sA = smem_base + (uint32_t)sc * STG_BYTES;
        const uint32_t sB = sA + STG_MAT;

#pragma unroll
        for (int ks = 0; ks < 2; ks++) {            // two k16 steps per BK=32
            const uint32_t kb = ks * 32;            // byte offset of k-step
            uint32_t afr[2][4];
            uint32_t bfr[8][2];
#pragma unroll
            for (int mi = 0; mi < 2; mi++) {
                uint32_t addr = sA + (uint32_t)((wm * 32 + mi * 16) * PH * 2) + kb + aOff;
                ldsm_x4(afr[mi][0], afr[mi][1], afr[mi][2], afr[mi][3], addr);
            }
#pragma unroll
            for (int p = 0; p < 4; p++) {
                uint32_t addr = sB + (uint32_t)((wn * 64 + p * 16) * PH * 2) + kb + bOff;
                ldsm_x4(bfr[2 * p][0], bfr[2 * p][1], bfr[2 * p + 1][0], bfr[2 * p + 1][1], addr);
            }
#pragma unroll
            for (int mi = 0; mi < 2; mi++)
#pragma unroll
                for (int ni = 0; ni < 8; ni++)
                    mma_f16(acc[mi][ni], afr[mi], bfr[ni]);
        }
        sc++; if (sc == STAGES) sc = 0;
        // no trailing barrier: 3-stage ring + top-of-loop barrier protect reuse
    }

    // Epilogue
    const float qscale = (MODE == 0 && z == 0) ? 0.125f : 1.0f;
#pragma unroll
    for (int mi = 0; mi < 2; mi++) {
#pragma unroll
        for (int ni = 0; ni < 8; ni++) {
            int r0 = m0 + wm * 32 + mi * 16 + (lane >> 2);
            int c0 = n0 + wn * 64 + ni * 8 + (lane & 3) * 2;
#pragma unroll
            for (int half2i = 0; half2i < 2; half2i++) {
                int m = r0 + half2i * 8;
                float v0 = (acc[mi][ni][2 * half2i]     + bz[c0])     * qscale;
                float v1 = (acc[mi][ni][2 * half2i + 1] + bz[c0 + 1]) * qscale;
                if (MODE == 0) {
                    int b = m >> 12;
                    int l = m & 4095;
                    int w = l >> 7, rr = l & 127;
                    int h = c0 >> 6, d = c0 & 63;
                    size_t idx = ((((size_t)((b * NW + w) * NHEAD + h)) * WIN + rr) * HDIM) + d;
                    __half2 hv = __floats2half2_rn(v0, v1);
                    *(__half2*)&g_qkv16[(size_t)z * QKV_STRIDE + idx] = hv;
                } else {
                    *(float2*)&Yp[(size_t)m * D_MODEL + c0] = make_float2(v0, v1);
                }
            }
        }
    }
}

// ---------------------------------------------------------------------------
// fp16 windowed attention. One CTA (256 thr, 8 warps) per (b,w,h).
// Warp w owns rows w*16..w*16+15; softmax entirely in registers (quad shfl).
// smem (halves): sq[128][72], sk[128][72], sv[128][72], sp[128][136]
// ---------------------------------------------------------------------------
#define VP 72                      // q/k/v pitch (halves): 144B, conflict-free
#define PP 136                     // P pitch (halves): 272B, conflict-free
#define SQB 0
#define SKB (128 * VP * 2)         // 18432
#define SVB (2 * 128 * VP * 2)     // 36864
#define SPB (3 * 128 * VP * 2)     // 55296
#define ATTN_SMEM (SPB + 128 * PP * 2)   // 90112 bytes

__global__ __launch_bounds__(256) void attn_kernel() {
    extern __shared__ uint8_t smem[];
    const uint32_t sbase = (uint32_t)__cvta_generic_to_shared(smem);

    const int bid = blockIdx.x;
    const int h = bid & 15;
    const int w = (bid >> 4) & 31;
    const int b = bid >> 9;
    const size_t tile = ((size_t)((b * NW + w) * NHEAD + h)) * (WIN * HDIM);

    const __half* gq = g_qkv16 + tile;
    const __half* gk = g_qkv16 + QKV_STRIDE + tile;
    const __half* gv = g_qkv16 + 2 * QKV_STRIDE + tile;

    const int tid = threadIdx.x;
    const int warp = tid >> 5, lane = tid & 31;

    // ---- stage q,k,v via cp.async ----
#pragma unroll
    for (int i = 0; i < 12; i++) {
        int ci = tid + i * 256;
        int mat = ci >> 10;               // 0=q 1=k 2=v
        int rc = ci & 1023;
        int row = rc >> 3;
        int c16 = rc & 7;
        const __half* src = (mat == 0) ? gq : (mat == 1) ? gk : gv;
        cp_async16(sbase + (uint32_t)(mat * (128 * VP * 2)) + row * (VP * 2) + c16 * 16,
                   src + row * HDIM + c16 * 8);
    }
    cp_commit();
    cp_wait<0>();
    __syncthreads();

    const uint32_t aOff = ((lane & 15) * VP + (lane >> 4) * 8) * 2;          // q rows
    const uint32_t bOff = ((((lane >> 4) << 3) + (lane & 7)) * VP + ((lane >> 3) & 1) * 8) * 2; // k rows
    const uint32_t aPOff = ((lane & 15) * PP + (lane >> 4) * 8) * 2;         // P rows
    const uint32_t vOff = ((((lane >> 3) & 1) * 8 + (lane & 7)) * VP + (lane >> 4) * 8) * 2;    // v trans

    const int mrow = warp * 16;

    // ---- QK^T: acc[16 ni][4], rows mrow..mrow+15 ----
    float acc[16][4];
#pragma unroll
    for (int ni = 0; ni < 16; ni++)
#pragma unroll
        for (int e = 0; e < 4; e++) acc[ni][e] = 0.f;

#pragma unroll
    for (int ks = 0; ks < 4; ks++) {              // 64 d = 4 k16 steps
        const uint32_t kb = ks * 32;
        uint32_t afr[4];
        ldsm_x4(afr[0], afr[1], afr[2], afr[3],
                sbase + SQB + (uint32_t)(mrow * VP * 2) + kb + aOff);
#pragma unroll
        for (int t = 0; t < 8; t++) {             // 128 j = 8 pairs of ni tiles
            uint32_t bfr[2][2];
            ldsm_x4(bfr[0][0], bfr[0][1], bfr[1][0], bfr[1][1],
                    sbase + SKB + (uint32_t)(t * 16 * VP * 2) + kb + bOff);
            mma_f16(acc[2 * t],     afr, bfr[0]);
            mma_f16(acc[2 * t + 1], afr, bfr[1]);
        }
    }

    // ---- softmax in registers (rows r0 = mrow+lane/4, r1 = r0+8) ----
    float mx0 = -1e30f, mx1 = -1e30f;
#pragma unroll
    for (int ni = 0; ni < 16; ni++) {
        mx0 = fmaxf(mx0, fmaxf(acc[ni][0], acc[ni][1]));
        mx1 = fmaxf(mx1, fmaxf(acc[ni][2], acc[ni][3]));
    }
    mx0 = fmaxf(mx0, __shfl_xor_sync(0xffffffff, mx0, 1));
    mx0 = fmaxf(mx0, __shfl_xor_sync(0xffffffff, mx0, 2));
    mx1 = fmaxf(mx1, __shfl_xor_sync(0xffffffff, mx1, 1));
    mx1 = fmaxf(mx1, __shfl_xor_sync(0xffffffff, mx1, 2));

    float sum0 = 0.f, sum1 = 0.f;
    const uint32_t spRow0 = sbase + SPB + (uint32_t)((mrow + (lane >> 2)) * PP + (lane & 3) * 2) * 2;
#pragma unroll
    for (int ni = 0; ni < 16; ni++) {
        float p0 = __expf(acc[ni][0] - mx0);
        float p1 = __expf(acc[ni][1] - mx0);
        float p2 = __expf(acc[ni][2] - mx1);
        float p3 = __expf(acc[ni][3] - mx1);
        sum0 += p0 + p1;
        sum1 += p2 + p3;
        __half2 h01 = __floats2half2_rn(p0, p1);
        __half2 h23 = __floats2half2_rn(p2, p3);
        asm volatile("st.shared.b32 [%0], %1;" :: "r"(spRow0 + ni * 16), "r"(*(uint32_t*)&h01));
        asm volatile("st.shared.b32 [%0], %1;" :: "r"(spRow0 + 8 * PP * 2 + ni * 16), "r"(*(uint32_t*)&h23));
    }
    sum0 += __shfl_xor_sync(0xffffffff, sum0, 1);
    sum0 += __shfl_xor_sync(0xffffffff, sum0, 2);
    sum1 += __shfl_xor_sync(0xffffffff, sum1, 1);
    sum1 += __shfl_xor_sync(0xffffffff, sum1, 2);
    const float inv0 = 1.f / sum0;
    const float inv1 = 1.f / sum1;
    __syncwarp();

    // ---- O = P @ V ----
    float oacc[8][4];
#pragma unroll
    for (int n = 0; n < 8; n++)
#pragma unroll
        for (int e = 0; e < 4; e++) oacc[n][e] = 0.f;

#pragma unroll
    for (int ks = 0; ks < 8; ks++) {              // 128 j
        uint32_t afr[4];
        ldsm_x4(afr[0], afr[1], afr[2], afr[3],
                sbase + SPB + (uint32_t)(mrow * PP * 2) + ks * 32 + aPOff);
#pragma unroll
        for (int dt = 0; dt < 4; dt++) {          // 64 d
            uint32_t bfr[2][2];
            ldsm_x4_t(bfr[0][0], bfr[0][1], bfr[1][0], bfr[1][1],
                      sbase + SVB + (uint32_t)(ks * 16 * VP * 2) + dt * 32 + vOff);
            mma_f16(oacc[2 * dt],     afr, bfr[0]);
            mma_f16(oacc[2 * dt + 1], afr, bfr[1]);
        }
    }

    // ---- epilogue: normalize, store half to g_attn16 ----
    const int r0 = mrow + (lane >> 2);
    const size_t gb0 = ((size_t)b * SEQ + (size_t)w * WIN + r0) * D_MODEL + h * HDIM;
    const size_t gb1 = gb0 + 8ull * D_MODEL;
#pragma unroll
    for (int n = 0; n < 8; n++) {
        const int c0 = n * 8 + (lane & 3) * 2;
        __half2 h0 = __floats2half2_rn(oacc[n][0] * inv0, oacc[n][1] * inv0);
        __half2 h1 = __floats2half2_rn(oacc[n][2] * inv1, oacc[n][3] * inv1);
        *(__half2*)&g_attn16[gb0 + c0] = h0;
        *(__half2*)&g_attn16[gb1 + c0] = h1;
    }
}

// ---------------------------------------------------------------------------
extern "C" void kernel_launch(void* const* d_in, const int* in_sizes, int n_in,
                              void* d_out, int out_size) {
    const float* q   = (const float*)d_in[0];
    const float* k   = (const float*)d_in[1];
    const float* v   = (const float*)d_in[2];
    const float* ipw = (const float*)d_in[3];
    const float* ipb = (const float*)d_in[4];
    const float* ow  = (const float*)d_in[5];
    const float* ob  = (const float*)d_in[6];
    float* out = (float*)d_out;

    cudaFuncSetAttribute(gemm_f16<0>, cudaFuncAttributeMaxDynamicSharedMemorySize, GEMM_SMEM);
    cudaFuncSetAttribute(gemm_f16<1>, cudaFuncAttributeMaxDynamicSharedMemorySize, GEMM_SMEM);
    cudaFuncSetAttribute(attn_kernel, cudaFuncAttributeMaxDynamicSharedMemorySize, ATTN_SMEM);

    __half* w16;  cudaGetSymbolAddress((void**)&w16,  g_w16);
    __half* ow16; cudaGetSymbolAddress((void**)&ow16, g_ow16);

    // 0) fp16 prepass (bandwidth, MLP=4)
    dim3 gc(1024, 3);
    cvt3<<<gc, 256>>>(q, k, v);
    cvt_half<<<512, 256>>>(ipw, w16, 3 * D_MODEL * D_MODEL / 4);
    cvt_half<<<256, 256>>>(ow,  ow16,    D_MODEL * D_MODEL / 4);

    // 1) QKV projection (Q scaled by 1/8 in epilogue)
    dim3 g0(D_MODEL / BN, M_TOTAL / BM, 3);
    gemm_f16<0><<<g0, 256, GEMM_SMEM>>>(ipb, nullptr);

    // 2) Windowed attention: 2048 blocks
    attn_kernel<<<BATCH * NW * NHEAD, 256, ATTN_SMEM>>>();

    // 3) Output projection
    dim3 g1(D_MODEL / BN, M_TOTAL / BM, 1);
    gemm_f16<1><<<g1, 256, GEMM_SMEM>>>(ob, out);
}

// round 16
// speedup vs baseline: 3.9517x; 1.0606x over previous
#include <cuda_runtime.h>
#include <cuda_fp16.h>
#include <cstdint>
#include <cstdio>

#define D_MODEL 1024
#define NHEAD   16
#define HDIM    64
#define WIN     128
#define BATCH   4
#define SEQ     4096
#define NW      (SEQ / WIN)            // 32
#define M_TOTAL (BATCH * SEQ)          // 16384
#define QKV_STRIDE ((size_t)M_TOTAL * D_MODEL)  // 16777216

// Scratch (allocation-free rule: device globals)
__device__ __half g_x16[3ull * M_TOTAL * D_MODEL];    // fp16 q,k,v inputs
__device__ __half g_w16[3ull * D_MODEL * D_MODEL];    // fp16 in_proj_w
__device__ __half g_ow16[(size_t)D_MODEL * D_MODEL];  // fp16 out_w
__device__ __half g_qkv16[3ull * M_TOTAL * D_MODEL];  // fp16 attention tiles (Q pre-scaled)
__device__ __half g_attn16[(size_t)M_TOTAL * D_MODEL];// fp16 attention output

// ---------------------------------------------------------------------------
// helpers (generic-target ISA only; tcgen05 rejected by harness ptxas sm_103)
// ---------------------------------------------------------------------------
__device__ __forceinline__ void mma_f16(float c[4], const uint32_t a[4], const uint32_t b[2]) {
    asm volatile(
        "mma.sync.aligned.m16n8k16.row.col.f32.f16.f16.f32 "
        "{%0,%1,%2,%3}, {%4,%5,%6,%7}, {%8,%9}, {%0,%1,%2,%3};\n"
        : "+f"(c[0]), "+f"(c[1]), "+f"(c[2]), "+f"(c[3])
        : "r"(a[0]), "r"(a[1]), "r"(a[2]), "r"(a[3]), "r"(b[0]), "r"(b[1]));
}

__device__ __forceinline__ void ldsm_x4(uint32_t& r0, uint32_t& r1, uint32_t& r2, uint32_t& r3,
                                        uint32_t saddr) {
    asm volatile("ldmatrix.sync.aligned.m8n8.x4.shared.b16 {%0,%1,%2,%3}, [%4];"
                 : "=r"(r0), "=r"(r1), "=r"(r2), "=r"(r3) : "r"(saddr));
}
__device__ __forceinline__ void ldsm_x4_t(uint32_t& r0, uint32_t& r1, uint32_t& r2, uint32_t& r3,
                                          uint32_t saddr) {
    asm volatile("ldmatrix.sync.aligned.m8n8.x4.trans.shared.b16 {%0,%1,%2,%3}, [%4];"
                 : "=r"(r0), "=r"(r1), "=r"(r2), "=r"(r3) : "r"(saddr));
}

__device__ __forceinline__ void cp_async16(uint32_t dst, const void* src) {
    asm volatile("cp.async.cg.shared.global [%0], [%1], 16;\n" :: "r"(dst), "l"(src));
}
__device__ __forceinline__ void cp_commit() { asm volatile("cp.async.commit_group;\n" ::: "memory"); }
template <int N>
__device__ __forceinline__ void cp_wait() { asm volatile("cp.async.wait_group %0;\n" :: "n"(N) : "memory"); }

// ---------------------------------------------------------------------------
// Prepass: fp32 -> fp16, MLP=8
// ---------------------------------------------------------------------------
__device__ __forceinline__ uint2 cvt4(float4 v) {
    __half2 lo = __floats2half2_rn(v.x, v.y);
    __half2 hi = __floats2half2_rn(v.z, v.w);
    return make_uint2(*(uint32_t*)&lo, *(uint32_t*)&hi);
}

__global__ __launch_bounds__(256) void cvt3(const float* __restrict__ q,
                                            const float* __restrict__ k,
                                            const float* __restrict__ v) {
    const int z = blockIdx.y;
    const float* src = (z == 0) ? q : (z == 1) ? k : v;
    __half* dst = g_x16 + (size_t)z * QKV_STRIDE;
    const int n4 = M_TOTAL * D_MODEL / 4;
    const int stride = gridDim.x * 256;
    int i = blockIdx.x * 256 + threadIdx.x;
    for (; i + 7 * stride < n4; i += 8 * stride) {
        float4 t[8];
#pragma unroll
        for (int u = 0; u < 8; u++) t[u] = *(const float4*)&src[4 * (i + u * stride)];
#pragma unroll
        for (int u = 0; u < 8; u++) *(uint2*)&dst[4 * (i + u * stride)] = cvt4(t[u]);
    }
    for (; i < n4; i += stride) *(uint2*)&dst[4 * i] = cvt4(*(const float4*)&src[4 * i]);
}

__global__ __launch_bounds__(256) void cvt_half(const float* __restrict__ src,
                                                __half* __restrict__ dst, int n4) {
    const int stride = gridDim.x * 256;
    int i = blockIdx.x * 256 + threadIdx.x;
    for (; i + 7 * stride < n4; i += 8 * stride) {
        float4 t[8];
#pragma unroll
        for (int u = 0; u < 8; u++) t[u] = *(const float4*)&src[4 * (i + u * stride)];
#pragma unroll
        for (int u = 0; u < 8; u++) *(uint2*)&dst[4 * (i + u * stride)] = cvt4(t[u]);
    }
    for (; i < n4; i += stride) *(uint2*)&dst[4 * i] = cvt4(*(const float4*)&src[4 * i]);
}

// ---------------------------------------------------------------------------
// fp16 GEMM: Y[M,N] = X[M,K] @ W[N,K]^T + bias   (TN, both K-contiguous)
// 256 threads (8 warps as 4x2), warp tile 32x64, block tile 128x128, BK=64.
// 2-stage cp.async ring, ONE barrier per K-tile (16 total), 2 CTAs/SM.
// ---------------------------------------------------------------------------
#define BM 128
#define BN 128
#define BK 64
#define PH 72                                 // halves pitch: 144B, conflict-free
#define STG_MAT (128 * PH * 2)                // 18432 B per matrix
#define STG_BYTES (2 * STG_MAT)               // 36864 B per stage
#define GEMM_SMEM (2 * STG_BYTES)             // 73728 B per CTA (2 CTAs = 144 KB)

template <int MODE>
__global__ __launch_bounds__(256, 2) void gemm_f16(
    const float* __restrict__ bp, float* __restrict__ Yp)
{
    extern __shared__ uint8_t smem[];
    const uint32_t smem_base = (uint32_t)__cvta_generic_to_shared(smem);

    const int z = blockIdx.z;
    const __half* X;
    const __half* Wz;
    const float* bz;
    if (MODE == 0) {
        X  = g_x16 + (size_t)z * QKV_STRIDE;
        Wz = g_w16 + (size_t)z * D_MODEL * D_MODEL;
        bz = bp + z * D_MODEL;
    } else {
        X  = g_attn16;
        Wz = g_ow16;
        bz = bp;
    }

    const int m0 = blockIdx.y * BM;
    const int n0 = blockIdx.x * BN;
    const int tid  = threadIdx.x;
    const int warp = tid >> 5, lane = tid & 31;
    const int wm = warp >> 1, wn = warp & 1;   // 4x2 warps, warp tile 32x64

    float acc[2][8][4];
#pragma unroll
    for (int mi = 0; mi < 2; mi++)
#pragma unroll
        for (int ni = 0; ni < 8; ni++)
#pragma unroll
            for (int r = 0; r < 4; r++) acc[mi][ni][r] = 0.f;

    // staging: 2048 x 16B chunks per stage, 8 per thread (A rows then B rows)
    uint32_t dsts[8];
    const __half* srcs[8];
#pragma unroll
    for (int i = 0; i < 8; i++) {
        int ci = tid + i * 256;
        int mat = ci >> 10;                 // 0=A, 1=B
        int rc = ci & 1023;
        int row = rc >> 3, c16 = rc & 7;
        dsts[i] = (uint32_t)(mat * STG_MAT + row * (PH * 2) + c16 * 16);
        srcs[i] = (mat == 0) ? &X [(size_t)(m0 + row) * D_MODEL + c16 * 8]
                             : &Wz[(size_t)(n0 + row) * D_MODEL + c16 * 8];
    }

    // fragment lane addressing (bytes)
    const uint32_t aOff = ((lane & 15) * PH + (lane >> 4) * 8) * 2;
    const uint32_t bOff = ((((lane >> 4) << 3) + (lane & 7)) * PH + ((lane >> 3) & 1) * 8) * 2;

    auto issue_stage = [&](int s, int kt) {
        const uint32_t sb = smem_base + (uint32_t)s * STG_BYTES;
#pragma unroll
        for (int i = 0; i < 8; i++) cp_async16(sb + dsts[i], srcs[i] + kt);
        cp_commit();
    };

    issue_stage(0, 0);
    int kt_load = BK;
    int sc = 0;

#pragma unroll 1
    for (int t = 0; t < D_MODEL / BK; t++) {
        cp_wait<0>();
        __syncthreads();   // stage sc ready; all warps done computing other slot

        if (kt_load < D_MODEL) {
            issue_stage(sc ^ 1, kt_load);
            kt_load += BK;
        }

        const uint32_t sA = smem_base + (uint32_t)sc * STG_BYTES;
        const uint32_t sB = sA + STG_MAT;

#pragma unroll
        for (int ks = 0; ks < 4; ks++) {            // four k16 steps per BK=64
            const uint32_t kb = ks * 32;            // byte offset of k-step
            uint32_t afr[2][4];
            uint32_t bfr[8][2];
#pragma unroll
            for (int mi = 0; mi < 2; mi++) {
                uint32_t addr = sA + (uint32_t)((wm * 32 + mi * 16) * PH * 2) + kb + aOff;
                ldsm_x4(afr[mi][0], afr[mi][1], afr[mi][2], afr[mi][3], addr);
            }
#pragma unroll
            for (int p = 0; p < 4; p++) {
                uint32_t addr = sB + (uint32_t)((wn * 64 + p * 16) * PH * 2) + kb + bOff;
                ldsm_x4(bfr[2 * p][0], bfr[2 * p][1], bfr[2 * p + 1][0], bfr[2 * p + 1][1], addr);
            }
#pragma unroll
            for (int mi = 0; mi < 2; mi++)
#pragma unroll
                for (int ni = 0; ni < 8; ni++)
                    mma_f16(acc[mi][ni], afr[mi], bfr[ni]);
        }
        sc ^= 1;
        // no trailing barrier: top-of-loop barrier protects slot reuse
    }

    // Epilogue
    const float qscale = (MODE == 0 && z == 0) ? 0.125f : 1.0f;
#pragma unroll
    for (int mi = 0; mi < 2; mi++) {
#pragma unroll
        for (int ni = 0; ni < 8; ni++) {
            int r0 = m0 + wm * 32 + mi * 16 + (lane >> 2);
            int c0 = n0 + wn * 64 + ni * 8 + (lane & 3) * 2;
#pragma unroll
            for (int half2i = 0; half2i < 2; half2i++) {
                int m = r0 + half2i * 8;
                float v0 = (acc[mi][ni][2 * half2i]     + bz[c0])     * qscale;
                float v1 = (acc[mi][ni][2 * half2i + 1] + bz[c0 + 1]) * qscale;
                if (MODE == 0) {
                    int b = m >> 12;
                    int l = m & 4095;
                    int w = l >> 7, rr = l & 127;
                    int h = c0 >> 6, d = c0 & 63;
                    size_t idx = ((((size_t)((b * NW + w) * NHEAD + h)) * WIN + rr) * HDIM) + d;
                    __half2 hv = __floats2half2_rn(v0, v1);
                    *(__half2*)&g_qkv16[(size_t)z * QKV_STRIDE + idx] = hv;
                } else {
                    *(float2*)&Yp[(size_t)m * D_MODEL + c0] = make_float2(v0, v1);
                }
            }
        }
    }
}

// ---------------------------------------------------------------------------
// fp16 windowed attention. One CTA (256 thr, 8 warps) per (b,w,h).
// Warp w owns rows w*16..w*16+15; softmax entirely in registers (quad shfl).
// smem (halves): sq[128][72], sk[128][72], sv[128][72], sp[128][136]
// ---------------------------------------------------------------------------
#define VP 72                      // q/k/v pitch (halves): 144B, conflict-free
#define PP 136                     // P pitch (halves): 272B, conflict-free
#define SQB 0
#define SKB (128 * VP * 2)         // 18432
#define SVB (2 * 128 * VP * 2)     // 36864
#define SPB (3 * 128 * VP * 2)     // 55296
#define ATTN_SMEM (SPB + 128 * PP * 2)   // 90112 bytes

__global__ __launch_bounds__(256) void attn_kernel() {
    extern __shared__ uint8_t smem[];
    const uint32_t sbase = (uint32_t)__cvta_generic_to_shared(smem);

    const int bid = blockIdx.x;
    const int h = bid & 15;
    const int w = (bid >> 4) & 31;
    const int b = bid >> 9;
    const size_t tile = ((size_t)((b * NW + w) * NHEAD + h)) * (WIN * HDIM);

    const __half* gq = g_qkv16 + tile;
    const __half* gk = g_qkv16 + QKV_STRIDE + tile;
    const __half* gv = g_qkv16 + 2 * QKV_STRIDE + tile;

    const int tid = threadIdx.x;
    const int warp = tid >> 5, lane = tid & 31;

    // ---- stage q,k,v via cp.async ----
#pragma unroll
    for (int i = 0; i < 12; i++) {
        int ci = tid + i * 256;
        int mat = ci >> 10;               // 0=q 1=k 2=v
        int rc = ci & 1023;
        int row = rc >> 3;
        int c16 = rc & 7;
        const __half* src = (mat == 0) ? gq : (mat == 1) ? gk : gv;
        cp_async16(sbase + (uint32_t)(mat * (128 * VP * 2)) + row * (VP * 2) + c16 * 16,
                   src + row * HDIM + c16 * 8);
    }
    cp_commit();
    cp_wait<0>();
    __syncthreads();

    const uint32_t aOff = ((lane & 15) * VP + (lane >> 4) * 8) * 2;          // q rows
    const uint32_t bOff = ((((lane >> 4) << 3) + (lane & 7)) * VP + ((lane >> 3) & 1) * 8) * 2; // k rows
    const uint32_t aPOff = ((lane & 15) * PP + (lane >> 4) * 8) * 2;         // P rows
    const uint32_t vOff = ((((lane >> 3) & 1) * 8 + (lane & 7)) * VP + (lane >> 4) * 8) * 2;    // v trans

    const int mrow = warp * 16;

    // ---- QK^T: acc[16 ni][4], rows mrow..mrow+15 ----
    float acc[16][4];
#pragma unroll
    for (int ni = 0; ni < 16; ni++)
#pragma unroll
        for (int e = 0; e < 4; e++) acc[ni][e] = 0.f;

#pragma unroll
    for (int ks = 0; ks < 4; ks++) {              // 64 d = 4 k16 steps
        const uint32_t kb = ks * 32;
        uint32_t afr[4];
        ldsm_x4(afr[0], afr[1], afr[2], afr[3],
                sbase + SQB + (uint32_t)(mrow * VP * 2) + kb + aOff);
#pragma unroll
        for (int t = 0; t < 8; t++) {             // 128 j = 8 pairs of ni tiles
            uint32_t bfr[2][2];
            ldsm_x4(bfr[0][0], bfr[0][1], bfr[1][0], bfr[1][1],
                    sbase + SKB + (uint32_t)(t * 16 * VP * 2) + kb + bOff);
            mma_f16(acc[2 * t],     afr, bfr[0]);
            mma_f16(acc[2 * t + 1], afr, bfr[1]);
        }
    }

    // ---- softmax in registers (rows r0 = mrow+lane/4, r1 = r0+8) ----
    float mx0 = -1e30f, mx1 = -1e30f;
#pragma unroll
    for (int ni = 0; ni < 16; ni++) {
        mx0 = fmaxf(mx0, fmaxf(acc[ni][0], acc[ni][1]));
        mx1 = fmaxf(mx1, fmaxf(acc[ni][2], acc[ni][3]));
    }
    mx0 = fmaxf(mx0, __shfl_xor_sync(0xffffffff, mx0, 1));
    mx0 = fmaxf(mx0, __shfl_xor_sync(0xffffffff, mx0, 2));
    mx1 = fmaxf(mx1, __shfl_xor_sync(0xffffffff, mx1, 1));
    mx1 = fmaxf(mx1, __shfl_xor_sync(0xffffffff, mx1, 2));

    float sum0 = 0.f, sum1 = 0.f;
    const uint32_t spRow0 = sbase + SPB + (uint32_t)((mrow + (lane >> 2)) * PP + (lane & 3) * 2) * 2;
#pragma unroll
    for (int ni = 0; ni < 16; ni++) {
        float p0 = __expf(acc[ni][0] - mx0);
        float p1 = __expf(acc[ni][1] - mx0);
        float p2 = __expf(acc[ni][2] - mx1);
        float p3 = __expf(acc[ni][3] - mx1);
        sum0 += p0 + p1;
        sum1 += p2 + p3;
        __half2 h01 = __floats2half2_rn(p0, p1);
        __half2 h23 = __floats2half2_rn(p2, p3);
        asm volatile("st.shared.b32 [%0], %1;" :: "r"(spRow0 + ni * 16), "r"(*(uint32_t*)&h01));
        asm volatile("st.shared.b32 [%0], %1;" :: "r"(spRow0 + 8 * PP * 2 + ni * 16), "r"(*(uint32_t*)&h23));
    }
    sum0 += __shfl_xor_sync(0xffffffff, sum0, 1);
    sum0 += __shfl_xor_sync(0xffffffff, sum0, 2);
    sum1 += __shfl_xor_sync(0xffffffff, sum1, 1);
    sum1 += __shfl_xor_sync(0xffffffff, sum1, 2);
    const float inv0 = 1.f / sum0;
    const float inv1 = 1.f / sum1;
    __syncwarp();

    // ---- O = P @ V ----
    float oacc[8][4];
#pragma unroll
    for (int n = 0; n < 8; n++)
#pragma unroll
        for (int e = 0; e < 4; e++) oacc[n][e] = 0.f;

#pragma unroll
    for (int ks = 0; ks < 8; ks++) {              // 128 j
        uint32_t afr[4];
        ldsm_x4(afr[0], afr[1], afr[2], afr[3],
                sbase + SPB + (uint32_t)(mrow * PP * 2) + ks * 32 + aPOff);
#pragma unroll
        for (int dt = 0; dt < 4; dt++) {          // 64 d
            uint32_t bfr[2][2];
            ldsm_x4_t(bfr[0][0], bfr[0][1], bfr[1][0], bfr[1][1],
                      sbase + SVB + (uint32_t)(ks * 16 * VP * 2) + dt * 32 + vOff);
            mma_f16(oacc[2 * dt],     afr, bfr[0]);
            mma_f16(oacc[2 * dt + 1], afr, bfr[1]);
        }
    }

    // ---- epilogue: normalize, store half to g_attn16 ----
    const int r0 = mrow + (lane >> 2);
    const size_t gb0 = ((size_t)b * SEQ + (size_t)w * WIN + r0) * D_MODEL + h * HDIM;
    const size_t gb1 = gb0 + 8ull * D_MODEL;
#pragma unroll
    for (int n = 0; n < 8; n++) {
        const int c0 = n * 8 + (lane & 3) * 2;
        __half2 h0 = __floats2half2_rn(oacc[n][0] * inv0, oacc[n][1] * inv0);
        __half2 h1 = __floats2half2_rn(oacc[n][2] * inv1, oacc[n][3] * inv1);
        *(__half2*)&g_attn16[gb0 + c0] = h0;
        *(__half2*)&g_attn16[gb1 + c0] = h1;
    }
}

// ---------------------------------------------------------------------------
extern "C" void kernel_launch(void* const* d_in, const int* in_sizes, int n_in,
                              void* d_out, int out_size) {
    const float* q   = (const float*)d_in[0];
    const float* k   = (const float*)d_in[1];
    const float* v   = (const float*)d_in[2];
    const float* ipw = (const float*)d_in[3];
    const float* ipb = (const float*)d_in[4];
    const float* ow  = (const float*)d_in[5];
    const float* ob  = (const float*)d_in[6];
    float* out = (float*)d_out;

    cudaFuncSetAttribute(gemm_f16<0>, cudaFuncAttributeMaxDynamicSharedMemorySize, GEMM_SMEM);
    cudaFuncSetAttribute(gemm_f16<1>, cudaFuncAttributeMaxDynamicSharedMemorySize, GEMM_SMEM);
    cudaFuncSetAttribute(attn_kernel, cudaFuncAttributeMaxDynamicSharedMemorySize, ATTN_SMEM);

    __half* w16;  cudaGetSymbolAddress((void**)&w16,  g_w16);
    __half* ow16; cudaGetSymbolAddress((void**)&ow16, g_ow16);

    // 0) fp16 prepass (bandwidth, MLP=8)
    dim3 gc(1024, 3);
    cvt3<<<gc, 256>>>(q, k, v);
    cvt_half<<<512, 256>>>(ipw, w16, 3 * D_MODEL * D_MODEL / 4);
    cvt_half<<<256, 256>>>(ow,  ow16,    D_MODEL * D_MODEL / 4);

    // 1) QKV projection (Q scaled by 1/8 in epilogue)
    dim3 g0(D_MODEL / BN, M_TOTAL / BM, 3);
    gemm_f16<0><<<g0, 256, GEMM_SMEM>>>(ipb, nullptr);

    // 2) Windowed attention: 2048 blocks
    attn_kernel<<<BATCH * NW * NHEAD, 256, ATTN_SMEM>>>();

    // 3) Output projection
    dim3 g1(D_MODEL / BN, M_TOTAL / BM, 1);
    gemm_f16<1><<<g1, 256, GEMM_SMEM>>>(ob, out);
}

// round 17
// speedup vs baseline: 4.0368x; 1.0216x over previous
#include <cuda_runtime.h>
#include <cuda_fp16.h>
#include <cstdint>
#include <cstdio>

#define D_MODEL 1024
#define NHEAD   16
#define HDIM    64
#define WIN     128
#define BATCH   4
#define SEQ     4096
#define NW      (SEQ / WIN)            // 32
#define M_TOTAL (BATCH * SEQ)          // 16384
#define QKV_STRIDE ((size_t)M_TOTAL * D_MODEL)  // 16777216

// Scratch (allocation-free rule: device globals)
__device__ __half g_x16[3ull * M_TOTAL * D_MODEL];    // fp16 q,k,v inputs
__device__ __half g_w16[3ull * D_MODEL * D_MODEL];    // fp16 in_proj_w
__device__ __half g_ow16[(size_t)D_MODEL * D_MODEL];  // fp16 out_w
__device__ __half g_qkv16[3ull * M_TOTAL * D_MODEL];  // fp16 attention tiles (Q pre-scaled)
__device__ __half g_attn16[(size_t)M_TOTAL * D_MODEL];// fp16 attention output

// ---------------------------------------------------------------------------
// helpers (generic-target ISA only; tcgen05 rejected by harness ptxas sm_103)
// ---------------------------------------------------------------------------
__device__ __forceinline__ void mma_f16(float c[4], const uint32_t a[4], const uint32_t b[2]) {
    asm volatile(
        "mma.sync.aligned.m16n8k16.row.col.f32.f16.f16.f32 "
        "{%0,%1,%2,%3}, {%4,%5,%6,%7}, {%8,%9}, {%0,%1,%2,%3};\n"
        : "+f"(c[0]), "+f"(c[1]), "+f"(c[2]), "+f"(c[3])
        : "r"(a[0]), "r"(a[1]), "r"(a[2]), "r"(a[3]), "r"(b[0]), "r"(b[1]));
}

__device__ __forceinline__ void ldsm_x4(uint32_t& r0, uint32_t& r1, uint32_t& r2, uint32_t& r3,
                                        uint32_t saddr) {
    asm volatile("ldmatrix.sync.aligned.m8n8.x4.shared.b16 {%0,%1,%2,%3}, [%4];"
                 : "=r"(r0), "=r"(r1), "=r"(r2), "=r"(r3) : "r"(saddr));
}
__device__ __forceinline__ void ldsm_x4_t(uint32_t& r0, uint32_t& r1, uint32_t& r2, uint32_t& r3,
                                          uint32_t saddr) {
    asm volatile("ldmatrix.sync.aligned.m8n8.x4.trans.shared.b16 {%0,%1,%2,%3}, [%4];"
                 : "=r"(r0), "=r"(r1), "=r"(r2), "=r"(r3) : "r"(saddr));
}

__device__ __forceinline__ void cp_async16(uint32_t dst, const void* src) {
    asm volatile("cp.async.cg.shared.global [%0], [%1], 16;\n" :: "r"(dst), "l"(src));
}
__device__ __forceinline__ void cp_commit() { asm volatile("cp.async.commit_group;\n" ::: "memory"); }
template <int N>
__device__ __forceinline__ void cp_wait() { asm volatile("cp.async.wait_group %0;\n" :: "n"(N) : "memory"); }

// ---------------------------------------------------------------------------
// Prepass: fp32 -> fp16, MLP=8
// ---------------------------------------------------------------------------
__device__ __forceinline__ uint2 cvt4(float4 v) {
    __half2 lo = __floats2half2_rn(v.x, v.y);
    __half2 hi = __floats2half2_rn(v.z, v.w);
    return make_uint2(*(uint32_t*)&lo, *(uint32_t*)&hi);
}

__global__ __launch_bounds__(256) void cvt3(const float* __restrict__ q,
                                            const float* __restrict__ k,
                                            const float* __restrict__ v) {
    const int z = blockIdx.y;
    const float* src = (z == 0) ? q : (z == 1) ? k : v;
    __half* dst = g_x16 + (size_t)z * QKV_STRIDE;
    const int n4 = M_TOTAL * D_MODEL / 4;
    const int stride = gridDim.x * 256;
    int i = blockIdx.x * 256 + threadIdx.x;
    for (; i + 7 * stride < n4; i += 8 * stride) {
        float4 t[8];
#pragma unroll
        for (int u = 0; u < 8; u++) t[u] = *(const float4*)&src[4 * (i + u * stride)];
#pragma unroll
        for (int u = 0; u < 8; u++) *(uint2*)&dst[4 * (i + u * stride)] = cvt4(t[u]);
    }
    for (; i < n4; i += stride) *(uint2*)&dst[4 * i] = cvt4(*(const float4*)&src[4 * i]);
}

__global__ __launch_bounds__(256) void cvt_half(const float* __restrict__ src,
                                                __half* __restrict__ dst, int n4) {
    const int stride = gridDim.x * 256;
    int i = blockIdx.x * 256 + threadIdx.x;
    for (; i + 7 * stride < n4; i += 8 * stride) {
        float4 t[8];
#pragma unroll
        for (int u = 0; u < 8; u++) t[u] = *(const float4*)&src[4 * (i + u * stride)];
#pragma unroll
        for (int u = 0; u < 8; u++) *(uint2*)&dst[4 * (i + u * stride)] = cvt4(t[u]);
    }
    for (; i < n4; i += stride) *(uint2*)&dst[4 * i] = cvt4(*(const float4*)&src[4 * i]);
}

// ---------------------------------------------------------------------------
// fp16 GEMM: Y[M,N] = X[M,K] @ W[N,K]^T + bias   (TN, both K-contiguous)
// 128 threads (4 warps, 4x1), warp tile 32x64, block tile 128x64, BK=64.
// 2-stage cp.async ring, ONE barrier per K-tile, 4 CTAs/SM (4 independent
// barrier domains of 4 warps -> latency hiding across CTAs).
// ---------------------------------------------------------------------------
#define BM 128
#define BN 64
#define BK 64
#define PH 72                                 // halves pitch: 144B, conflict-free
#define STG_A (128 * PH * 2)                  // 18432 B
#define STG_B (64 * PH * 2)                   // 9216 B
#define STG_BYTES (STG_A + STG_B)             // 27648 B per stage
#define GEMM_SMEM (2 * STG_BYTES)             // 55296 B per CTA (4 CTAs = 221 KB)

template <int MODE>
__global__ __launch_bounds__(128, 4) void gemm_f16(
    const float* __restrict__ bp, float* __restrict__ Yp)
{
    extern __shared__ uint8_t smem[];
    const uint32_t smem_base = (uint32_t)__cvta_generic_to_shared(smem);

    const int z = blockIdx.z;
    const __half* X;
    const __half* Wz;
    const float* bz;
    if (MODE == 0) {
        X  = g_x16 + (size_t)z * QKV_STRIDE;
        Wz = g_w16 + (size_t)z * D_MODEL * D_MODEL;
        bz = bp + z * D_MODEL;
    } else {
        X  = g_attn16;
        Wz = g_ow16;
        bz = bp;
    }

    const int m0 = blockIdx.y * BM;
    const int n0 = blockIdx.x * BN;
    const int tid  = threadIdx.x;
    const int warp = tid >> 5, lane = tid & 31;
    const int wm = warp;                       // 4x1 warps, warp tile 32x64

    float acc[2][8][4];
#pragma unroll
    for (int mi = 0; mi < 2; mi++)
#pragma unroll
        for (int ni = 0; ni < 8; ni++)
#pragma unroll
            for (int r = 0; r < 4; r++) acc[mi][ni][r] = 0.f;

    // staging: 1536 x 16B chunks per stage, 12 per thread (A 1024 then B 512)
    uint32_t dsts[12];
    const __half* srcs[12];
#pragma unroll
    for (int i = 0; i < 12; i++) {
        int ci = tid + i * 128;
        if (ci < 1024) {
            int row = ci >> 3, c16 = ci & 7;
            dsts[i] = (uint32_t)(row * (PH * 2) + c16 * 16);
            srcs[i] = &X[(size_t)(m0 + row) * D_MODEL + c16 * 8];
        } else {
            int bi = ci - 1024;
            int row = bi >> 3, c16 = bi & 7;
            dsts[i] = (uint32_t)(STG_A + row * (PH * 2) + c16 * 16);
            srcs[i] = &Wz[(size_t)(n0 + row) * D_MODEL + c16 * 8];
        }
    }

    // fragment lane addressing (bytes)
    const uint32_t aOff = ((lane & 15) * PH + (lane >> 4) * 8) * 2;
    const uint32_t bOff = ((((lane >> 4) << 3) + (lane & 7)) * PH + ((lane >> 3) & 1) * 8) * 2;

    auto issue_stage = [&](int s, int kt) {
        const uint32_t sb = smem_base + (uint32_t)s * STG_BYTES;
#pragma unroll
        for (int i = 0; i < 12; i++) cp_async16(sb + dsts[i], srcs[i] + kt);
        cp_commit();
    };

    issue_stage(0, 0);
    int kt_load = BK;
    int sc = 0;

#pragma unroll 1
    for (int t = 0; t < D_MODEL / BK; t++) {
        cp_wait<0>();
        __syncthreads();   // stage sc ready; all warps done computing other slot

        if (kt_load < D_MODEL) {
            issue_stage(sc ^ 1, kt_load);
            kt_load += BK;
        }

        const uint32_t sA = smem_base + (uint32_t)sc * STG_BYTES;
        const uint32_t sB = sA + STG_A;

#pragma unroll
        for (int ks = 0; ks < 4; ks++) {            // four k16 steps per BK=64
            const uint32_t kb = ks * 32;            // byte offset of k-step
            uint32_t afr[2][4];
            uint32_t bfr[8][2];
#pragma unroll
            for (int mi = 0; mi < 2; mi++) {
                uint32_t addr = sA + (uint32_t)((wm * 32 + mi * 16) * PH * 2) + kb + aOff;
                ldsm_x4(afr[mi][0], afr[mi][1], afr[mi][2], afr[mi][3], addr);
            }
#pragma unroll
            for (int p = 0; p < 4; p++) {
                uint32_t addr = sB + (uint32_t)((p * 16) * PH * 2) + kb + bOff;
                ldsm_x4(bfr[2 * p][0], bfr[2 * p][1], bfr[2 * p + 1][0], bfr[2 * p + 1][1], addr);
            }
#pragma unroll
            for (int mi = 0; mi < 2; mi++)
#pragma unroll
                for (int ni = 0; ni < 8; ni++)
                    mma_f16(acc[mi][ni], afr[mi], bfr[ni]);
        }
        sc ^= 1;
        // no trailing barrier: top-of-loop barrier protects slot reuse
    }

    // Epilogue
    const float qscale = (MODE == 0 && z == 0) ? 0.125f : 1.0f;
#pragma unroll
    for (int mi = 0; mi < 2; mi++) {
#pragma unroll
        for (int ni = 0; ni < 8; ni++) {
            int r0 = m0 + wm * 32 + mi * 16 + (lane >> 2);
            int c0 = n0 + ni * 8 + (lane & 3) * 2;
#pragma unroll
            for (int half2i = 0; half2i < 2; half2i++) {
                int m = r0 + half2i * 8;
                float v0 = (acc[mi][ni][2 * half2i]     + bz[c0])     * qscale;
                float v1 = (acc[mi][ni][2 * half2i + 1] + bz[c0 + 1]) * qscale;
                if (MODE == 0) {
                    int b = m >> 12;
                    int l = m & 4095;
                    int w = l >> 7, rr = l & 127;
                    int h = c0 >> 6, d = c0 & 63;
                    size_t idx = ((((size_t)((b * NW + w) * NHEAD + h)) * WIN + rr) * HDIM) + d;
                    __half2 hv = __floats2half2_rn(v0, v1);
                    *(__half2*)&g_qkv16[(size_t)z * QKV_STRIDE + idx] = hv;
                } else {
                    *(float2*)&Yp[(size_t)m * D_MODEL + c0] = make_float2(v0, v1);
                }
            }
        }
    }
}

// ---------------------------------------------------------------------------
// fp16 windowed attention. One CTA (256 thr, 8 warps) per (b,w,h).
// Warp w owns rows w*16..w*16+15; softmax entirely in registers (quad shfl).
// smem (halves): sq[128][72], sk[128][72], sv[128][72], sp[128][136]
// ---------------------------------------------------------------------------
#define VP 72                      // q/k/v pitch (halves): 144B, conflict-free
#define PP 136                     // P pitch (halves): 272B, conflict-free
#define SQB 0
#define SKB (128 * VP * 2)         // 18432
#define SVB (2 * 128 * VP * 2)     // 36864
#define SPB (3 * 128 * VP * 2)     // 55296
#define ATTN_SMEM (SPB + 128 * PP * 2)   // 90112 bytes

__global__ __launch_bounds__(256) void attn_kernel() {
    extern __shared__ uint8_t smem[];
    const uint32_t sbase = (uint32_t)__cvta_generic_to_shared(smem);

    const int bid = blockIdx.x;
    const int h = bid & 15;
    const int w = (bid >> 4) & 31;
    const int b = bid >> 9;
    const size_t tile = ((size_t)((b * NW + w) * NHEAD + h)) * (WIN * HDIM);

    const __half* gq = g_qkv16 + tile;
    const __half* gk = g_qkv16 + QKV_STRIDE + tile;
    const __half* gv = g_qkv16 + 2 * QKV_STRIDE + tile;

    const int tid = threadIdx.x;
    const int warp = tid >> 5, lane = tid & 31;

    // ---- stage q,k,v via cp.async ----
#pragma unroll
    for (int i = 0; i < 12; i++) {
        int ci = tid + i * 256;
        int mat = ci >> 10;               // 0=q 1=k 2=v
        int rc = ci & 1023;
        int row = rc >> 3;
        int c16 = rc & 7;
        const __half* src = (mat == 0) ? gq : (mat == 1) ? gk : gv;
        cp_async16(sbase + (uint32_t)(mat * (128 * VP * 2)) + row * (VP * 2) + c16 * 16,
                   src + row * HDIM + c16 * 8);
    }
    cp_commit();
    cp_wait<0>();
    __syncthreads();

    const uint32_t aOff = ((lane & 15) * VP + (lane >> 4) * 8) * 2;          // q rows
    const uint32_t bOff = ((((lane >> 4) << 3) + (lane & 7)) * VP + ((lane >> 3) & 1) * 8) * 2; // k rows
    const uint32_t aPOff = ((lane & 15) * PP + (lane >> 4) * 8) * 2;         // P rows
    const uint32_t vOff = ((((lane >> 3) & 1) * 8 + (lane & 7)) * VP + (lane >> 4) * 8) * 2;    // v trans

    const int mrow = warp * 16;

    // ---- QK^T: acc[16 ni][4], rows mrow..mrow+15 ----
    float acc[16][4];
#pragma unroll
    for (int ni = 0; ni < 16; ni++)
#pragma unroll
        for (int e = 0; e < 4; e++) acc[ni][e] = 0.f;

#pragma unroll
    for (int ks = 0; ks < 4; ks++) {              // 64 d = 4 k16 steps
        const uint32_t kb = ks * 32;
        uint32_t afr[4];
        ldsm_x4(afr[0], afr[1], afr[2], afr[3],
                sbase + SQB + (uint32_t)(mrow * VP * 2) + kb + aOff);
#pragma unroll
        for (int t = 0; t < 8; t++) {             // 128 j = 8 pairs of ni tiles
            uint32_t bfr[2][2];
            ldsm_x4(bfr[0][0], bfr[0][1], bfr[1][0], bfr[1][1],
                    sbase + SKB + (uint32_t)(t * 16 * VP * 2) + kb + bOff);
            mma_f16(acc[2 * t],     afr, bfr[0]);
            mma_f16(acc[2 * t + 1], afr, bfr[1]);
        }
    }

    // ---- softmax in registers (rows r0 = mrow+lane/4, r1 = r0+8) ----
    float mx0 = -1e30f, mx1 = -1e30f;
#pragma unroll
    for (int ni = 0; ni < 16; ni++) {
        mx0 = fmaxf(mx0, fmaxf(acc[ni][0], acc[ni][1]));
        mx1 = fmaxf(mx1, fmaxf(acc[ni][2], acc[ni][3]));
    }
    mx0 = fmaxf(mx0, __shfl_xor_sync(0xffffffff, mx0, 1));
    mx0 = fmaxf(mx0, __shfl_xor_sync(0xffffffff, mx0, 2));
    mx1 = fmaxf(mx1, __shfl_xor_sync(0xffffffff, mx1, 1));
    mx1 = fmaxf(mx1, __shfl_xor_sync(0xffffffff, mx1, 2));

    float sum0 = 0.f, sum1 = 0.f;
    const uint32_t spRow0 = sbase + SPB + (uint32_t)((mrow + (lane >> 2)) * PP + (lane & 3) * 2) * 2;
#pragma unroll
    for (int ni = 0; ni < 16; ni++) {
        float p0 = __expf(acc[ni][0] - mx0);
        float p1 = __expf(acc[ni][1] - mx0);
        float p2 = __expf(acc[ni][2] - mx1);
        float p3 = __expf(acc[ni][3] - mx1);
        sum0 += p0 + p1;
        sum1 += p2 + p3;
        __half2 h01 = __floats2half2_rn(p0, p1);
        __half2 h23 = __floats2half2_rn(p2, p3);
        asm volatile("st.shared.b32 [%0], %1;" :: "r"(spRow0 + ni * 16), "r"(*(uint32_t*)&h01));
        asm volatile("st.shared.b32 [%0], %1;" :: "r"(spRow0 + 8 * PP * 2 + ni * 16), "r"(*(uint32_t*)&h23));
    }
    sum0 += __shfl_xor_sync(0xffffffff, sum0, 1);
    sum0 += __shfl_xor_sync(0xffffffff, sum0, 2);
    sum1 += __shfl_xor_sync(0xffffffff, sum1, 1);
    sum1 += __shfl_xor_sync(0xffffffff, sum1, 2);
    const float inv0 = 1.f / sum0;
    const float inv1 = 1.f / sum1;
    __syncwarp();

    // ---- O = P @ V ----
    float oacc[8][4];
#pragma unroll
    for (int n = 0; n < 8; n++)
#pragma unroll
        for (int e = 0; e < 4; e++) oacc[n][e] = 0.f;

#pragma unroll
    for (int ks = 0; ks < 8; ks++) {              // 128 j
        uint32_t afr[4];
        ldsm_x4(afr[0], afr[1], afr[2], afr[3],
                sbase + SPB + (uint32_t)(mrow * PP * 2) + ks * 32 + aPOff);
#pragma unroll
        for (int dt = 0; dt < 4; dt++) {          // 64 d
            uint32_t bfr[2][2];
            ldsm_x4_t(bfr[0][0], bfr[0][1], bfr[1][0], bfr[1][1],
                      sbase + SVB + (uint32_t)(ks * 16 * VP * 2) + dt * 32 + vOff);
            mma_f16(oacc[2 * dt],     afr, bfr[0]);
            mma_f16(oacc[2 * dt + 1], afr, bfr[1]);
        }
    }

    // ---- epilogue: normalize, store half to g_attn16 ----
    const int r0 = mrow + (lane >> 2);
    const size_t gb0 = ((size_t)b * SEQ + (size_t)w * WIN + r0) * D_MODEL + h * HDIM;
    const size_t gb1 = gb0 + 8ull * D_MODEL;
#pragma unroll
    for (int n = 0; n < 8; n++) {
        const int c0 = n * 8 + (lane & 3) * 2;
        __half2 h0 = __floats2half2_rn(oacc[n][0] * inv0, oacc[n][1] * inv0);
        __half2 h1 = __floats2half2_rn(oacc[n][2] * inv1, oacc[n][3] * inv1);
        *(__half2*)&g_attn16[gb0 + c0] = h0;
        *(__half2*)&g_attn16[gb1 + c0] = h1;
    }
}

// ---------------------------------------------------------------------------
extern "C" void kernel_launch(void* const* d_in, const int* in_sizes, int n_in,
                              void* d_out, int out_size) {
    const float* q   = (const float*)d_in[0];
    const float* k   = (const float*)d_in[1];
    const float* v   = (const float*)d_in[2];
    const float* ipw = (const float*)d_in[3];
    const float* ipb = (const float*)d_in[4];
    const float* ow  = (const float*)d_in[5];
    const float* ob  = (const float*)d_in[6];
    float* out = (float*)d_out;

    cudaFuncSetAttribute(gemm_f16<0>, cudaFuncAttributeMaxDynamicSharedMemorySize, GEMM_SMEM);
    cudaFuncSetAttribute(gemm_f16<1>, cudaFuncAttributeMaxDynamicSharedMemorySize, GEMM_SMEM);
    cudaFuncSetAttribute(attn_kernel, cudaFuncAttributeMaxDynamicSharedMemorySize, ATTN_SMEM);

    __half* w16;  cudaGetSymbolAddress((void**)&w16,  g_w16);
    __half* ow16; cudaGetSymbolAddress((void**)&ow16, g_ow16);

    // 0) fp16 prepass (bandwidth, MLP=8)
    dim3 gc(1024, 3);
    cvt3<<<gc, 256>>>(q, k, v);
    cvt_half<<<512, 256>>>(ipw, w16, 3 * D_MODEL * D_MODEL / 4);
    cvt_half<<<256, 256>>>(ow,  ow16,    D_MODEL * D_MODEL / 4);

    // 1) QKV projection (Q scaled by 1/8 in epilogue)
    dim3 g0(D_MODEL / BN, M_TOTAL / BM, 3);
    gemm_f16<0><<<g0, 128, GEMM_SMEM>>>(ipb, nullptr);

    // 2) Windowed attention: 2048 blocks
    attn_kernel<<<BATCH * NW * NHEAD, 256, ATTN_SMEM>>>();

    // 3) Output projection
    dim3 g1(D_MODEL / BN, M_TOTAL / BM, 1);
    gemm_f16<1><<<g1, 128, GEMM_SMEM>>>(ob, out);
}